// round 13
// baseline (speedup 1.0000x reference)
#include <cuda_runtime.h>
#include <cstdint>

// ---------------- problem constants ----------------
#define B      32
#define C0     16
#define H0     128
#define W0     128
#define C1     64
#define NTOK   4096
#define NS     256
#define MT     128          // tokens per MMA CTA
#define THR    0.02f        // near-tie rescue threshold (abs score gap)

// ---------------- scratch ----------------
__device__ __align__(16) float  g_xtok[B * NTOK * C1];      // [b][n][c]
__device__ __align__(16) float  g_xs  [B * NS * C1];        // [b][m][c]
__device__ __align__(16) float  g_m2  [B * NS];             // -0.5*|xs|^2
__device__ __align__(16) float  g_wt2 [C1 * 3 * C1];        // [(k*64+o)*64 + c]
__device__ __align__(16) float  g_y   [B * NS * 3 * C1];    // [pair][k*64+o]
__device__ __align__(16) int4   g_idx [B * NTOK];
__device__ int g_flagcnt;
__device__ int g_flags[B * NTOK];

__device__ const int SAMP[16] = {0,4,8,13,17,21,25,29,34,38,42,46,50,55,59,63};

#define FMA2(a,x,y) asm("fma.rn.f32x2 %0, %1, %2, %0;" : "+l"(a) : "l"(x), "l"(y))
#define UNPK(lo,hi,a) asm("mov.b64 {%0,%1}, %2;" : "=f"(lo), "=f"(hi) : "l"(a))

// tf32 hi/lo split: v = hi + lo + O(2^-22 * v)
__device__ __forceinline__ float2 tf32_split(float v) {
    uint32_t hb, lb;
    asm("cvt.rna.tf32.f32 %0, %1;" : "=r"(hb) : "f"(v));
    float hi = __uint_as_float(hb);
    float r = v - hi;
    asm("cvt.rna.tf32.f32 %0, %1;" : "=r"(lb) : "f"(r));
    return make_float2(hi, __uint_as_float(lb));
}

// smem layout for score_mma (floats, pitch 132 => conflict-free frag LDS)
#define PITCH    132
#define SB_F     0                       // B_ext: 256 rows x PITCH (hi 0..63, lo 64..127)
#define SA_F     (NS * PITCH)            // A_ext: 128 rows x PITCH
#define SM2_F    (SA_F + MT * PITCH)     // 256 floats
#define SMEM_F   (SM2_F + NS)
#define SMEM_MMA (SMEM_F * 4)
// merge scratch reuses A region after mainloop: 4096 floats + 4096 ints < 16896
#define SV_F     SA_F
#define SI_F     (SA_F + 4096)

// tie-break: matches stable top_k (smaller sample index wins ties)
#define BETTER(s, i, cv, ci) (((s) > (cv)) || ((s) == (cv) && (i) < (ci)))
#define INSERT3(s, idx) do { \
    bool _g0 = BETTER(s, idx, t0, i0), _g1 = BETTER(s, idx, t1, i1), _g2 = BETTER(s, idx, t2, i2); \
    t2 = _g1 ? t1 : (_g2 ? (s) : t2);  i2 = _g1 ? i1 : (_g2 ? (idx) : i2); \
    t1 = _g0 ? t0 : (_g1 ? (s) : t1);  i1 = _g0 ? i0 : (_g1 ? (idx) : i1); \
    t0 = _g0 ? (s) : t0;               i0 = _g0 ? (idx) : i0; \
} while (0)
#define INSERT4(s, idx) do { \
    bool _g0 = BETTER(s, idx, t0, i0), _g1 = BETTER(s, idx, t1, i1); \
    bool _g2 = BETTER(s, idx, t2, i2), _g3 = BETTER(s, idx, t3, i3); \
    t3 = _g2 ? t2 : (_g3 ? (s) : t3);  i3 = _g2 ? i2 : (_g3 ? (idx) : i3); \
    t2 = _g1 ? t1 : (_g2 ? (s) : t2);  i2 = _g1 ? i1 : (_g2 ? (idx) : i2); \
    t1 = _g0 ? t0 : (_g1 ? (s) : t1);  i1 = _g0 ? i0 : (_g1 ? (idx) : i1); \
    t0 = _g0 ? (s) : t0;               i0 = _g0 ? (idx) : i0; \
} while (0)

// ---------------- kernel 1: pixel_unshuffle ----------------
__global__ __launch_bounds__(256) void unshuffle_kernel(const float* __restrict__ x) {
    __shared__ __align__(16) float s[128 * 33];
    int b  = blockIdx.x >> 6;
    int h1 = blockIdx.x & 63;
    int t  = threadIdx.x;
    const float* xb = x + (size_t)b * C0 * H0 * W0;
    #pragma unroll
    for (int i = 0; i < 4; i++) {
        int idx = t + 256 * i;
        int r   = idx >> 5;
        int w4  = idx & 31;
        int c = r >> 1, sh = r & 1;
        float4 v = *(const float4*)(xb + ((size_t)c * H0 + (2 * h1 + sh)) * W0 + w4 * 4);
        s[(4 * w4 + 0) * 33 + r] = v.x;
        s[(4 * w4 + 1) * 33 + r] = v.y;
        s[(4 * w4 + 2) * 33 + r] = v.z;
        s[(4 * w4 + 3) * 33 + r] = v.w;
    }
    __syncthreads();
    float* dst = g_xtok + ((size_t)b * NTOK + h1 * 64) * C1;
    #pragma unroll
    for (int i = 0; i < 4; i++) {
        int idx = t + 256 * i;
        int w1 = idx >> 4, q = idx & 15;
        int r0 = (2 * w1) * 33, r1 = (2 * w1 + 1) * 33;
        *(float4*)(dst + idx * 4) = make_float4(
            s[r0 + 2 * q],     s[r1 + 2 * q],
            s[r0 + 2 * q + 1], s[r1 + 2 * q + 1]);
    }
}

// ---------------- kernel 2: sampled tokens + (-0.5*m2) ----------------
__global__ void sample_kernel(const float* __restrict__ x) {
    int pair = blockIdx.x;
    int b = pair >> 8, m = pair & 255;
    int h1 = SAMP[m >> 4], w1 = SAMP[m & 15];
    int c1 = threadIdx.x;
    int c = c1 >> 2, sh = (c1 >> 1) & 1, sw = c1 & 1;
    float v = x[((size_t)(b * C0 + c) * H0 + (2 * h1 + sh)) * W0 + (2 * w1 + sw)];
    g_xs[(size_t)pair * C1 + c1] = v;
    __shared__ float red[64];
    red[c1] = v * v;
    __syncthreads();
    if (c1 < 32) {
        float s = red[c1] + red[c1 + 32];
        #pragma unroll
        for (int off = 16; off; off >>= 1)
            s += __shfl_down_sync(0xffffffffu, s, off);
        if (c1 == 0) g_m2[pair] = -0.5f * s;
    }
}

// ---------------- kernel 3: weight -> [k][o][c] + flag counter reset ----------------
__global__ void wt_kernel(const float* __restrict__ w) {
    int d = blockIdx.x * 256 + threadIdx.x;
    if (d == 0) g_flagcnt = 0;
    int c = d & 63;
    int ko = d >> 6;
    int o = ko & 63, k = ko >> 6;
    g_wt2[d] = w[o * 192 + c * 3 + k];
}

// ---------------- kernel 4 (ncu slot 4): HMMA 3-term tf32 GEMM + top-4 + flag --------
__global__ __launch_bounds__(256) void score_mma_kernel() {
    extern __shared__ __align__(16) float sm[];
    float* sB  = sm + SB_F;
    float* sA  = sm + SA_F;
    float* sM2 = sm + SM2_F;
    const int t = threadIdx.x;
    const int w = t >> 5, lane = t & 31;
    const int g = lane >> 2, q = lane & 3;
    const int b = blockIdx.y;
    const int tok0 = blockIdx.x * MT;

    const float4* asrc = (const float4*)(g_xtok + ((size_t)b * NTOK + tok0) * C1);
    #pragma unroll
    for (int i = 0; i < 8; i++) {
        int idx = t + 256 * i;
        float4 v = asrc[idx];
        int row = idx >> 4, c0 = (idx & 15) * 4;
        float2 s0 = tf32_split(v.x), s1 = tf32_split(v.y);
        float2 s2 = tf32_split(v.z), s3 = tf32_split(v.w);
        *(float4*)&sA[row * PITCH + c0]      = make_float4(s0.x, s1.x, s2.x, s3.x);
        *(float4*)&sA[row * PITCH + 64 + c0] = make_float4(s0.y, s1.y, s2.y, s3.y);
    }
    const float4* bsrc = (const float4*)(g_xs + (size_t)b * NS * C1);
    #pragma unroll
    for (int i = 0; i < 16; i++) {
        int idx = t + 256 * i;
        float4 v = bsrc[idx];
        int row = idx >> 4, c0 = (idx & 15) * 4;
        float2 s0 = tf32_split(v.x), s1 = tf32_split(v.y);
        float2 s2 = tf32_split(v.z), s3 = tf32_split(v.w);
        *(float4*)&sB[row * PITCH + c0]      = make_float4(s0.x, s1.x, s2.x, s3.x);
        *(float4*)&sB[row * PITCH + 64 + c0] = make_float4(s0.y, s1.y, s2.y, s3.y);
    }
    sM2[t] = g_m2[b * NS + t];
    __syncthreads();

    float c[128];
    #pragma unroll
    for (int i = 0; i < 128; i++) c[i] = 0.f;
    const int nbase = w * 32;

    #pragma unroll 1
    for (int kt = 0; kt < 24; kt++) {
        const int ks = (kt & 7) * 8;
        const int ka = ks + ((kt >= 8 && kt < 16) ? 64 : 0);
        const int kb = ks + ((kt >= 16) ? 64 : 0);
        uint32_t bf[8];
        #pragma unroll
        for (int nt = 0; nt < 4; nt++) {
            const float* bp = &sB[(nbase + nt * 8 + g) * PITCH + kb + q];
            bf[nt * 2]     = __float_as_uint(bp[0]);
            bf[nt * 2 + 1] = __float_as_uint(bp[4]);
        }
        #pragma unroll
        for (int mt = 0; mt < 8; mt++) {
            const float* ap = &sA[(mt * 16 + g) * PITCH + ka + q];
            uint32_t a0 = __float_as_uint(ap[0]);
            uint32_t a1 = __float_as_uint(ap[8 * PITCH]);
            uint32_t a2 = __float_as_uint(ap[4]);
            uint32_t a3 = __float_as_uint(ap[8 * PITCH + 4]);
            #pragma unroll
            for (int nt = 0; nt < 4; nt++) {
                float* cc = &c[(mt * 4 + nt) * 4];
                asm volatile(
                    "mma.sync.aligned.m16n8k8.row.col.f32.tf32.tf32.f32 "
                    "{%0,%1,%2,%3}, {%4,%5,%6,%7}, {%8,%9}, {%0,%1,%2,%3};"
                    : "+f"(cc[0]), "+f"(cc[1]), "+f"(cc[2]), "+f"(cc[3])
                    : "r"(a0), "r"(a1), "r"(a2), "r"(a3),
                      "r"(bf[nt * 2]), "r"(bf[nt * 2 + 1]));
            }
        }
    }

    int   smp[8];
    float m2v[8];
    #pragma unroll
    for (int nt = 0; nt < 4; nt++) {
        smp[nt * 2]     = nbase + nt * 8 + q * 2;
        smp[nt * 2 + 1] = smp[nt * 2] + 1;
        m2v[nt * 2]     = sM2[smp[nt * 2]];
        m2v[nt * 2 + 1] = sM2[smp[nt * 2 + 1]];
    }
    __syncthreads();   // reuse sA as merge scratch

    float* sv = sm + SV_F;
    int*   si = (int*)(sm + SI_F);

    #pragma unroll
    for (int mt = 0; mt < 8; mt++) {
        #pragma unroll
        for (int half = 0; half < 2; half++) {
            int row = mt * 16 + g + half * 8;
            float t0 = -3.4e38f, t1 = -3.4e38f, t2 = -3.4e38f, t3 = -3.4e38f;
            int   i0 = 0, i1 = 0, i2 = 0, i3 = 0;
            #pragma unroll
            for (int nt = 0; nt < 4; nt++) {
                #pragma unroll
                for (int e = 0; e < 2; e++) {
                    float s = c[(mt * 4 + nt) * 4 + half * 2 + e] + m2v[nt * 2 + e];
                    INSERT4(s, smp[nt * 2 + e]);
                }
            }
            #pragma unroll
            for (int dx = 1; dx <= 2; dx <<= 1) {
                float o0 = __shfl_xor_sync(~0u, t0, dx), o1 = __shfl_xor_sync(~0u, t1, dx);
                float o2 = __shfl_xor_sync(~0u, t2, dx), o3 = __shfl_xor_sync(~0u, t3, dx);
                int   j0 = __shfl_xor_sync(~0u, i0, dx), j1 = __shfl_xor_sync(~0u, i1, dx);
                int   j2 = __shfl_xor_sync(~0u, i2, dx), j3 = __shfl_xor_sync(~0u, i3, dx);
                INSERT4(o0, j0); INSERT4(o1, j1); INSERT4(o2, j2); INSERT4(o3, j3);
            }
            if (q == 0) {
                int base = (row * 8 + w) * 4;
                sv[base] = t0; sv[base + 1] = t1; sv[base + 2] = t2; sv[base + 3] = t3;
                si[base] = i0; si[base + 1] = i1; si[base + 2] = i2; si[base + 3] = i3;
            }
        }
    }
    __syncthreads();

    if (t < MT) {
        float t0 = -3.4e38f, t1 = -3.4e38f, t2 = -3.4e38f, t3 = -3.4e38f;
        int   i0 = 0, i1 = 0, i2 = 0, i3 = 0;
        #pragma unroll
        for (int wi = 0; wi < 8; wi++) {
            #pragma unroll
            for (int j = 0; j < 4; j++) {
                float s = sv[(t * 8 + wi) * 4 + j];
                int idx = si[(t * 8 + wi) * 4 + j];
                INSERT4(s, idx);
            }
        }
        int tokid = b * NTOK + tok0 + t;
        g_idx[tokid] = make_int4(i0, i1, i2, 0);
        if ((t0 - t1 < THR) || (t1 - t2 < THR) || (t2 - t3 < THR)) {
            int pos = atomicAdd(&g_flagcnt, 1);
            g_flags[pos] = tokid;
        }
    }
}

// ---------------- kernel 5: rescue with R7-BIT-IDENTICAL fp32 arithmetic -------------
// 8 chains mapped exactly as R7's four f32x2 accumulators (c0 seeded with -0.5*m2),
// merged ((c0+c4)+(c2+c6)) + ((c1+c5)+(c3+c7)) — reproduces the passing R7 scores.
__global__ __launch_bounds__(256) void rescue_kernel() {
    int cnt = g_flagcnt;
    if (cnt > B * NTOK) cnt = B * NTOK;
    const int nwarp = (gridDim.x * blockDim.x) >> 5;
    const int wgid  = (blockIdx.x * blockDim.x + threadIdx.x) >> 5;
    const int lane  = threadIdx.x & 31;

    for (int f = wgid; f < cnt; f += nwarp) {
        const int tokid = g_flags[f] & (B * NTOK - 1);
        const int b = tokid >> 12;                          // NTOK = 4096
        float tv[64];
        const float4* tp = (const float4*)(g_xtok + (size_t)tokid * C1);
        #pragma unroll
        for (int j = 0; j < 16; j++) {
            float4 v = tp[j];
            tv[4 * j] = v.x; tv[4 * j + 1] = v.y; tv[4 * j + 2] = v.z; tv[4 * j + 3] = v.w;
        }
        float t0 = -3.4e38f, t1 = -3.4e38f, t2 = -3.4e38f;
        int   i0 = 0, i1 = 0, i2 = 0;
        #pragma unroll 1
        for (int mi = 0; mi < 8; mi++) {
            int m = mi * 32 + lane;
            const float4* xp = (const float4*)(g_xs + ((size_t)b * NS + m) * C1);
            // chains = R7's FMA2 lanes: c0=a0.lo(ch 8j+0, init -m2/2), c1=a0.hi(8j+1),
            // c2=a1.lo(8j+2), c3=a1.hi(8j+3), c4=a2.lo(8j+4), c5=a2.hi(8j+5),
            // c6=a3.lo(8j+6), c7=a3.hi(8j+7)
            float c0 = g_m2[b * NS + m];
            float c1 = 0.f, c2 = 0.f, c3 = 0.f, c4 = 0.f, c5 = 0.f, c6 = 0.f, c7 = 0.f;
            #pragma unroll
            for (int j = 0; j < 8; j++) {
                float4 xa = xp[2 * j];          // sample channels 8j .. 8j+3
                float4 xb = xp[2 * j + 1];      // sample channels 8j+4 .. 8j+7
                c0 = fmaf(tv[8 * j + 0], xa.x, c0);
                c1 = fmaf(tv[8 * j + 1], xa.y, c1);
                c2 = fmaf(tv[8 * j + 2], xa.z, c2);
                c3 = fmaf(tv[8 * j + 3], xa.w, c3);
                c4 = fmaf(tv[8 * j + 4], xb.x, c4);
                c5 = fmaf(tv[8 * j + 5], xb.y, c5);
                c6 = fmaf(tv[8 * j + 6], xb.z, c6);
                c7 = fmaf(tv[8 * j + 7], xb.w, c7);
            }
            // R7 merge tree: ADD2(a0,a2); ADD2(a1,a3); ADD2(a0,a1); s = lo + hi
            float slo = (c0 + c4) + (c2 + c6);
            float shi = (c1 + c5) + (c3 + c7);
            float s = slo + shi;
            INSERT3(s, m);
        }
        #pragma unroll
        for (int dx = 16; dx; dx >>= 1) {
            float o0 = __shfl_xor_sync(~0u, t0, dx), o1 = __shfl_xor_sync(~0u, t1, dx), o2 = __shfl_xor_sync(~0u, t2, dx);
            int   j0 = __shfl_xor_sync(~0u, i0, dx), j1 = __shfl_xor_sync(~0u, i1, dx), j2 = __shfl_xor_sync(~0u, i2, dx);
            INSERT3(o0, j0); INSERT3(o1, j1); INSERT3(o2, j2);
        }
        if (lane == 0) g_idx[tokid] = make_int4(i0, i1, i2, 0);
    }
}

// ---------------- kernel 6: Y[pair][k*64+o] (+bias), 256 blocks x 32 pairs ----------
__global__ __launch_bounds__(192) void y_kernel(const float* __restrict__ bias) {
    int t = threadIdx.x;
    int o = t & 63;
    unsigned long long wq[32];
    const ulonglong2* wp = (const ulonglong2*)(g_wt2 + (size_t)t * 64);
    #pragma unroll
    for (int j = 0; j < 16; j++) { ulonglong2 v = wp[j]; wq[2 * j] = v.x; wq[2 * j + 1] = v.y; }

    __shared__ __align__(16) float s_xs[32 * 64];
    const float4* src = (const float4*)(g_xs + (size_t)blockIdx.x * 32 * 64);
    for (int i = t; i < 512; i += 192) ((float4*)s_xs)[i] = src[i];
    __syncthreads();

    float bo = (t < 64) ? bias[o] : 0.f;
    float* yb = g_y + (size_t)blockIdx.x * 32 * 192;
    #pragma unroll 1
    for (int p0 = 0; p0 < 32; p0 += 8) {
        unsigned long long acc[8] = {0,0,0,0,0,0,0,0};
        #pragma unroll
        for (int jj = 0; jj < 16; jj++) {
            #pragma unroll
            for (int p = 0; p < 8; p++) {
                ulonglong2 xq = *(const ulonglong2*)&s_xs[(p0 + p) * 64 + 4 * jj];
                FMA2(acc[p], wq[2 * jj],     xq.x);
                FMA2(acc[p], wq[2 * jj + 1], xq.y);
            }
        }
        #pragma unroll
        for (int p = 0; p < 8; p++) {
            float lo, hi; UNPK(lo, hi, acc[p]);
            yb[(size_t)(p0 + p) * 192 + t] = lo + hi + bo;
        }
    }
}

// ---------------- kernel 7: gather Y by idx, add, pixel_shuffle write ----------------
__global__ __launch_bounds__(256) void gather_out_kernel(float* __restrict__ out) {
    const int b = blockIdx.y;
    const int n = blockIdx.x * 256 + threadIdx.x;
    int4 id = g_idx[(size_t)b * NTOK + n];

    float4 acc[16];
    const float4* y0 = (const float4*)(g_y + ((size_t)(b * NS) + id.x) * 192);
    #pragma unroll
    for (int j = 0; j < 16; j++) acc[j] = y0[j];
    const float4* y1 = (const float4*)(g_y + ((size_t)(b * NS) + id.y) * 192 + 64);
    #pragma unroll
    for (int j = 0; j < 16; j++) {
        float4 v = y1[j];
        acc[j].x += v.x; acc[j].y += v.y; acc[j].z += v.z; acc[j].w += v.w;
    }
    const float4* y2 = (const float4*)(g_y + ((size_t)(b * NS) + id.z) * 192 + 128);
    #pragma unroll
    for (int j = 0; j < 16; j++) {
        float4 v = y2[j];
        acc[j].x += v.x; acc[j].y += v.y; acc[j].z += v.z; acc[j].w += v.w;
    }

    int h1 = n >> 6, w1 = n & 63;
    float* ob = out + (size_t)b * C0 * (H0 * W0);
    #pragma unroll
    for (int co = 0; co < 16; co++) {
        *(float2*)(ob + co * (H0 * W0) + (2 * h1)     * W0 + 2 * w1) = make_float2(acc[co].x, acc[co].y);
        *(float2*)(ob + co * (H0 * W0) + (2 * h1 + 1) * W0 + 2 * w1) = make_float2(acc[co].z, acc[co].w);
    }
}

// ---------------- launcher (score_mma in slot 4 so ncu captures it) ----------------
extern "C" void kernel_launch(void* const* d_in, const int* in_sizes, int n_in,
                              void* d_out, int out_size) {
    const float* x    = (const float*)d_in[0];
    const float* w    = (const float*)d_in[1];
    const float* bias = (const float*)d_in[2];
    float* out = (float*)d_out;

    cudaFuncSetAttribute(score_mma_kernel,
                         cudaFuncAttributeMaxDynamicSharedMemorySize, SMEM_MMA);

    unshuffle_kernel<<<B * 64, 256>>>(x);
    sample_kernel<<<B * NS, 64>>>(x);
    wt_kernel<<<48, 256>>>(w);
    score_mma_kernel<<<dim3(NTOK / MT, B), 256, SMEM_MMA>>>();
    rescue_kernel<<<256, 256>>>();
    y_kernel<<<B * NS / 32, 192>>>(bias);
    gather_out_kernel<<<dim3(NTOK / 256, B), 256>>>(out);
}

// round 14
// speedup vs baseline: 5.7727x; 5.7727x over previous
#include <cuda_runtime.h>
#include <cstdint>

// ---------------- problem constants ----------------
#define B      32
#define C0     16
#define H0     128
#define W0     128
#define C1     64
#define NTOK   4096
#define NS     256
#define MT     128          // tokens per MMA CTA
#define THR    3e-4f        // near-tie rescue threshold (~10x worst MMA error)

// ---------------- scratch ----------------
__device__ __align__(16) float  g_xtok[B * NTOK * C1];      // [b][n][c]
__device__ __align__(16) float  g_xs  [B * NS * C1];        // [b][m][c]
__device__ __align__(16) float  g_m2  [B * NS];             // -0.5*|xs|^2
__device__ __align__(16) float  g_wt2 [C1 * 3 * C1];        // [(k*64+o)*64 + c]
__device__ __align__(16) float  g_y   [B * NS * 3 * C1];    // [pair][k*64+o]
__device__ __align__(16) int4   g_idx [B * NTOK];
__device__ int g_flagcnt;
__device__ int g_flags[B * NTOK];

__device__ const int SAMP[16] = {0,4,8,13,17,21,25,29,34,38,42,46,50,55,59,63};

#define FMA2(a,x,y) asm("fma.rn.f32x2 %0, %1, %2, %0;" : "+l"(a) : "l"(x), "l"(y))
#define UNPK(lo,hi,a) asm("mov.b64 {%0,%1}, %2;" : "=f"(lo), "=f"(hi) : "l"(a))

// tf32 hi/lo split
__device__ __forceinline__ float2 tf32_split(float v) {
    uint32_t hb, lb;
    asm("cvt.rna.tf32.f32 %0, %1;" : "=r"(hb) : "f"(v));
    float hi = __uint_as_float(hb);
    float r = v - hi;
    asm("cvt.rna.tf32.f32 %0, %1;" : "=r"(lb) : "f"(r));
    return make_float2(hi, __uint_as_float(lb));
}

// smem layout (floats): B_ext / A_ext for mainloop; D + merge lists reuse them after
#define PITCH    132
#define SB_F     0                       // B_ext: 256 x PITCH
#define SA_F     (NS * PITCH)            // A_ext: 128 x PITCH  (= 33792)
#define SM2_F    (SA_F + MT * PITCH)     // 256 floats          (= 50688)
#define SMEM_F   (SM2_F + NS)
#define SMEM_MMA (SMEM_F * 4)
// post-mainloop reuse: D[128][260] at 0 (33280 < SA_F+...), lists in old A region
#define DRP      260                     // D row pitch (half offset 130 -> bank-clean)
#define SV2_F    SA_F                    // 256*4 floats
#define SI2_F    (SA_F + 1024)           // 256*4 ints

// tie-break comparator (rescue only): smaller sample index wins exact ties
#define BETTER(s, i, cv, ci) (((s) > (cv)) || ((s) == (cv) && (i) < (ci)))
#define INSERT3(s, idx) do { \
    bool _g0 = BETTER(s, idx, t0, i0), _g1 = BETTER(s, idx, t1, i1), _g2 = BETTER(s, idx, t2, i2); \
    t2 = _g1 ? t1 : (_g2 ? (s) : t2);  i2 = _g1 ? i1 : (_g2 ? (idx) : i2); \
    t1 = _g0 ? t0 : (_g1 ? (s) : t1);  i1 = _g0 ? i0 : (_g1 ? (idx) : i1); \
    t0 = _g0 ? (s) : t0;               i0 = _g0 ? (idx) : i0; \
} while (0)
// simple top-4 insert: ascending-idx insertion order makes ties keep smaller idx
#define INS4(s, idx) do { \
    bool _g0 = (s) > t0, _g1 = (s) > t1, _g2 = (s) > t2, _g3 = (s) > t3; \
    t3 = _g2 ? t2 : (_g3 ? (s) : t3);  i3 = _g2 ? i2 : (_g3 ? (idx) : i3); \
    t2 = _g1 ? t1 : (_g2 ? (s) : t2);  i2 = _g1 ? i1 : (_g2 ? (idx) : i2); \
    t1 = _g0 ? t0 : (_g1 ? (s) : t1);  i1 = _g0 ? i0 : (_g1 ? (idx) : i1); \
    t0 = _g0 ? (s) : t0;               i0 = _g0 ? (idx) : i0; \
} while (0)

// ---------------- kernel 1: pixel_unshuffle ----------------
__global__ __launch_bounds__(256) void unshuffle_kernel(const float* __restrict__ x) {
    __shared__ __align__(16) float s[128 * 33];
    int b  = blockIdx.x >> 6;
    int h1 = blockIdx.x & 63;
    int t  = threadIdx.x;
    const float* xb = x + (size_t)b * C0 * H0 * W0;
    #pragma unroll
    for (int i = 0; i < 4; i++) {
        int idx = t + 256 * i;
        int r   = idx >> 5;
        int w4  = idx & 31;
        int c = r >> 1, sh = r & 1;
        float4 v = *(const float4*)(xb + ((size_t)c * H0 + (2 * h1 + sh)) * W0 + w4 * 4);
        s[(4 * w4 + 0) * 33 + r] = v.x;
        s[(4 * w4 + 1) * 33 + r] = v.y;
        s[(4 * w4 + 2) * 33 + r] = v.z;
        s[(4 * w4 + 3) * 33 + r] = v.w;
    }
    __syncthreads();
    float* dst = g_xtok + ((size_t)b * NTOK + h1 * 64) * C1;
    #pragma unroll
    for (int i = 0; i < 4; i++) {
        int idx = t + 256 * i;
        int w1 = idx >> 4, q = idx & 15;
        int r0 = (2 * w1) * 33, r1 = (2 * w1 + 1) * 33;
        *(float4*)(dst + idx * 4) = make_float4(
            s[r0 + 2 * q],     s[r1 + 2 * q],
            s[r0 + 2 * q + 1], s[r1 + 2 * q + 1]);
    }
}

// ---------------- kernel 2: sampled tokens + (-0.5*m2) ----------------
__global__ void sample_kernel(const float* __restrict__ x) {
    int pair = blockIdx.x;
    int b = pair >> 8, m = pair & 255;
    int h1 = SAMP[m >> 4], w1 = SAMP[m & 15];
    int c1 = threadIdx.x;
    int c = c1 >> 2, sh = (c1 >> 1) & 1, sw = c1 & 1;
    float v = x[((size_t)(b * C0 + c) * H0 + (2 * h1 + sh)) * W0 + (2 * w1 + sw)];
    g_xs[(size_t)pair * C1 + c1] = v;
    __shared__ float red[64];
    red[c1] = v * v;
    __syncthreads();
    if (c1 < 32) {
        float s = red[c1] + red[c1 + 32];
        #pragma unroll
        for (int off = 16; off; off >>= 1)
            s += __shfl_down_sync(0xffffffffu, s, off);
        if (c1 == 0) g_m2[pair] = -0.5f * s;
    }
}

// ---------------- kernel 3: weight -> [k][o][c] + flag counter reset ----------------
__global__ void wt_kernel(const float* __restrict__ w) {
    int d = blockIdx.x * 256 + threadIdx.x;
    if (d == 0) g_flagcnt = 0;
    int c = d & 63;
    int ko = d >> 6;
    int o = ko & 63, k = ko >> 6;
    g_wt2[d] = w[o * 192 + c * 3 + k];
}

// ---------------- kernel 4 (ncu slot 4): HMMA tf32 GEMM, 512 thr, smem-scan top-4 ----
__global__ __launch_bounds__(512) void score_mma_kernel() {
    extern __shared__ __align__(16) float sm[];
    float* sB  = sm + SB_F;
    float* sA  = sm + SA_F;
    float* sM2 = sm + SM2_F;
    const int t = threadIdx.x;
    const int w = t >> 5, lane = t & 31;
    const int g = lane >> 2, q = lane & 3;
    const int b = blockIdx.y;
    const int tok0 = blockIdx.x * MT;
    const int nslice = (w & 7) * 32;     // 32 samples per warp column-slice
    const int mrow0  = (w >> 3) * 64;    // warps 0-7: rows 0-63, 8-15: rows 64-127

    // ---- fill A_ext ----
    const float4* asrc = (const float4*)(g_xtok + ((size_t)b * NTOK + tok0) * C1);
    #pragma unroll
    for (int i = 0; i < 4; i++) {
        int idx = t + 512 * i;               // 0..2047
        float4 v = asrc[idx];
        int row = idx >> 4, c0 = (idx & 15) * 4;
        float2 s0 = tf32_split(v.x), s1 = tf32_split(v.y);
        float2 s2 = tf32_split(v.z), s3 = tf32_split(v.w);
        *(float4*)&sA[row * PITCH + c0]      = make_float4(s0.x, s1.x, s2.x, s3.x);
        *(float4*)&sA[row * PITCH + 64 + c0] = make_float4(s0.y, s1.y, s2.y, s3.y);
    }
    // ---- fill B_ext ----
    const float4* bsrc = (const float4*)(g_xs + (size_t)b * NS * C1);
    #pragma unroll
    for (int i = 0; i < 8; i++) {
        int idx = t + 512 * i;               // 0..4095
        float4 v = bsrc[idx];
        int row = idx >> 4, c0 = (idx & 15) * 4;
        float2 s0 = tf32_split(v.x), s1 = tf32_split(v.y);
        float2 s2 = tf32_split(v.z), s3 = tf32_split(v.w);
        *(float4*)&sB[row * PITCH + c0]      = make_float4(s0.x, s1.x, s2.x, s3.x);
        *(float4*)&sB[row * PITCH + 64 + c0] = make_float4(s0.y, s1.y, s2.y, s3.y);
    }
    if (t < 256) sM2[t] = g_m2[b * NS + t];
    __syncthreads();

    // ---- mainloop: 3 phases (hi*hi, lo*hi, hi*lo) x 8 k-steps; 4 mt x 4 nt per warp --
    float c[64];
    #pragma unroll
    for (int i = 0; i < 64; i++) c[i] = 0.f;
    const float* bbase = sB + (nslice + g) * PITCH + q;
    const float* abase = sA + (mrow0 + g) * PITCH + q;

    #pragma unroll 1
    for (int ph = 0; ph < 3; ph++) {
        const int ka = (ph == 1) ? 64 : 0;
        const int kb = (ph == 2) ? 64 : 0;
        #pragma unroll 1
        for (int ks = 0; ks < 64; ks += 8) {
            uint32_t bf[8];
            #pragma unroll
            for (int nt = 0; nt < 4; nt++) {
                const float* bp = bbase + nt * 8 * PITCH + kb + ks;
                bf[nt * 2]     = __float_as_uint(bp[0]);
                bf[nt * 2 + 1] = __float_as_uint(bp[4]);
            }
            #pragma unroll
            for (int mtl = 0; mtl < 4; mtl++) {
                const float* ap = abase + mtl * 16 * PITCH + ka + ks;
                uint32_t a0 = __float_as_uint(ap[0]);
                uint32_t a1 = __float_as_uint(ap[8 * PITCH]);
                uint32_t a2 = __float_as_uint(ap[4]);
                uint32_t a3 = __float_as_uint(ap[8 * PITCH + 4]);
                #pragma unroll
                for (int nt = 0; nt < 4; nt++) {
                    float* cc = &c[(mtl * 4 + nt) * 4];
                    asm volatile(
                        "mma.sync.aligned.m16n8k8.row.col.f32.tf32.tf32.f32 "
                        "{%0,%1,%2,%3}, {%4,%5,%6,%7}, {%8,%9}, {%0,%1,%2,%3};"
                        : "+f"(cc[0]), "+f"(cc[1]), "+f"(cc[2]), "+f"(cc[3])
                        : "r"(a0), "r"(a1), "r"(a2), "r"(a3),
                          "r"(bf[nt * 2]), "r"(bf[nt * 2 + 1]));
                }
            }
        }
    }

    // ---- m2 per owned column + adjusted D column (half-pad at 128) ----
    float m2v[8];
    int   colv[4];
    #pragma unroll
    for (int nt = 0; nt < 4; nt++) {
        int col = nslice + nt * 8 + q * 2;
        colv[nt] = col + ((col >= 128) ? 2 : 0);
        m2v[nt * 2]     = sM2[col];
        m2v[nt * 2 + 1] = sM2[col + 1];
    }
    __syncthreads();   // everyone done with sA/sB -> reuse as D + lists

    // ---- store scores (+m2) into D[128][DRP] ----
    float* D = sm;
    #pragma unroll
    for (int mtl = 0; mtl < 4; mtl++) {
        #pragma unroll
        for (int half = 0; half < 2; half++) {
            int row = mrow0 + mtl * 16 + g + half * 8;
            #pragma unroll
            for (int nt = 0; nt < 4; nt++) {
                float2 v = make_float2(
                    c[(mtl * 4 + nt) * 4 + half * 2]     + m2v[nt * 2],
                    c[(mtl * 4 + nt) * 4 + half * 2 + 1] + m2v[nt * 2 + 1]);
                *(float2*)&D[row * DRP + colv[nt]] = v;
            }
        }
    }
    __syncthreads();

    // ---- scan: thread t<256 scans half-row (row=t>>1, half=t&1), 128 scores --------
    float* sv2 = sm + SV2_F;
    int*   si2 = (int*)(sm + SI2_F);
    if (t < 256) {
        const float* drow = &D[t * 130];     // (t>>1)*260 + (t&1)*130
        const int ibase = (t & 1) * 128;
        float t0 = -3.4e38f, t1 = -3.4e38f, t2 = -3.4e38f, t3 = -3.4e38f;
        int   i0 = 0, i1 = 0, i2 = 0, i3 = 0;
        #pragma unroll
        for (int j = 0; j < 64; j++) {
            float2 v = *(const float2*)&drow[2 * j];
            INS4(v.x, ibase + 2 * j);
            INS4(v.y, ibase + 2 * j + 1);
        }
        sv2[t * 4] = t0; sv2[t * 4 + 1] = t1; sv2[t * 4 + 2] = t2; sv2[t * 4 + 3] = t3;
        si2[t * 4] = i0; si2[t * 4 + 1] = i1; si2[t * 4 + 2] = i2; si2[t * 4 + 3] = i3;
    }
    __syncthreads();

    // ---- final: thread t<128 merges its row's two half-lists (half0 first: ties ok) -
    if (t < MT) {
        float t0 = -3.4e38f, t1 = -3.4e38f, t2 = -3.4e38f, t3 = -3.4e38f;
        int   i0 = 0, i1 = 0, i2 = 0, i3 = 0;
        #pragma unroll
        for (int h = 0; h < 2; h++) {
            int ts = t * 2 + h;
            #pragma unroll
            for (int j = 0; j < 4; j++) INS4(sv2[ts * 4 + j], si2[ts * 4 + j]);
        }
        int tokid = b * NTOK + tok0 + t;
        g_idx[tokid] = make_int4(i0, i1, i2, 0);
        if ((t0 - t1 < THR) || (t1 - t2 < THR) || (t2 - t3 < THR)) {
            int pos = atomicAdd(&g_flagcnt, 1);
            g_flags[pos] = tokid;
        }
    }
}

// ---------------- kernel 5: rescue with R7-bit-identical fp32 arithmetic -------------
__global__ __launch_bounds__(256) void rescue_kernel() {
    int cnt = g_flagcnt;
    if (cnt > B * NTOK) cnt = B * NTOK;
    const int nwarp = (gridDim.x * blockDim.x) >> 5;
    const int wgid  = (blockIdx.x * blockDim.x + threadIdx.x) >> 5;
    const int lane  = threadIdx.x & 31;

    for (int f = wgid; f < cnt; f += nwarp) {
        const int tokid = g_flags[f] & (B * NTOK - 1);
        const int b = tokid >> 12;
        float tv[64];
        const float4* tp = (const float4*)(g_xtok + (size_t)tokid * C1);
        #pragma unroll
        for (int j = 0; j < 16; j++) {
            float4 v = tp[j];
            tv[4 * j] = v.x; tv[4 * j + 1] = v.y; tv[4 * j + 2] = v.z; tv[4 * j + 3] = v.w;
        }
        float t0 = -3.4e38f, t1 = -3.4e38f, t2 = -3.4e38f;
        int   i0 = 0, i1 = 0, i2 = 0;
        #pragma unroll 1
        for (int mi = 0; mi < 8; mi++) {
            int m = mi * 32 + lane;
            const float4* xp = (const float4*)(g_xs + ((size_t)b * NS + m) * C1);
            float c0 = g_m2[b * NS + m];
            float c1 = 0.f, c2 = 0.f, c3 = 0.f, c4 = 0.f, c5 = 0.f, c6 = 0.f, c7 = 0.f;
            #pragma unroll
            for (int j = 0; j < 8; j++) {
                float4 xa = xp[2 * j];
                float4 xb = xp[2 * j + 1];
                c0 = fmaf(tv[8 * j + 0], xa.x, c0);
                c1 = fmaf(tv[8 * j + 1], xa.y, c1);
                c2 = fmaf(tv[8 * j + 2], xa.z, c2);
                c3 = fmaf(tv[8 * j + 3], xa.w, c3);
                c4 = fmaf(tv[8 * j + 4], xb.x, c4);
                c5 = fmaf(tv[8 * j + 5], xb.y, c5);
                c6 = fmaf(tv[8 * j + 6], xb.z, c6);
                c7 = fmaf(tv[8 * j + 7], xb.w, c7);
            }
            float slo = (c0 + c4) + (c2 + c6);
            float shi = (c1 + c5) + (c3 + c7);
            float s = slo + shi;
            INSERT3(s, m);
        }
        #pragma unroll
        for (int dx = 16; dx; dx >>= 1) {
            float o0 = __shfl_xor_sync(~0u, t0, dx), o1 = __shfl_xor_sync(~0u, t1, dx), o2 = __shfl_xor_sync(~0u, t2, dx);
            int   j0 = __shfl_xor_sync(~0u, i0, dx), j1 = __shfl_xor_sync(~0u, i1, dx), j2 = __shfl_xor_sync(~0u, i2, dx);
            INSERT3(o0, j0); INSERT3(o1, j1); INSERT3(o2, j2);
        }
        if (lane == 0) g_idx[tokid] = make_int4(i0, i1, i2, 0);
    }
}

// ---------------- kernel 6: Y[pair][k*64+o] (+bias), 256 blocks x 32 pairs ----------
__global__ __launch_bounds__(192) void y_kernel(const float* __restrict__ bias) {
    int t = threadIdx.x;
    int o = t & 63;
    unsigned long long wq[32];
    const ulonglong2* wp = (const ulonglong2*)(g_wt2 + (size_t)t * 64);
    #pragma unroll
    for (int j = 0; j < 16; j++) { ulonglong2 v = wp[j]; wq[2 * j] = v.x; wq[2 * j + 1] = v.y; }

    __shared__ __align__(16) float s_xs[32 * 64];
    const float4* src = (const float4*)(g_xs + (size_t)blockIdx.x * 32 * 64);
    for (int i = t; i < 512; i += 192) ((float4*)s_xs)[i] = src[i];
    __syncthreads();

    float bo = (t < 64) ? bias[o] : 0.f;
    float* yb = g_y + (size_t)blockIdx.x * 32 * 192;
    #pragma unroll 1
    for (int p0 = 0; p0 < 32; p0 += 8) {
        unsigned long long acc[8] = {0,0,0,0,0,0,0,0};
        #pragma unroll
        for (int jj = 0; jj < 16; jj++) {
            #pragma unroll
            for (int p = 0; p < 8; p++) {
                ulonglong2 xq = *(const ulonglong2*)&s_xs[(p0 + p) * 64 + 4 * jj];
                FMA2(acc[p], wq[2 * jj],     xq.x);
                FMA2(acc[p], wq[2 * jj + 1], xq.y);
            }
        }
        #pragma unroll
        for (int p = 0; p < 8; p++) {
            float lo, hi; UNPK(lo, hi, acc[p]);
            yb[(size_t)(p0 + p) * 192 + t] = lo + hi + bo;
        }
    }
}

// ---------------- kernel 7: gather Y by idx, add, pixel_shuffle write ----------------
__global__ __launch_bounds__(256) void gather_out_kernel(float* __restrict__ out) {
    const int b = blockIdx.y;
    const int n = blockIdx.x * 256 + threadIdx.x;
    int4 id = g_idx[(size_t)b * NTOK + n];

    float4 acc[16];
    const float4* y0 = (const float4*)(g_y + ((size_t)(b * NS) + id.x) * 192);
    #pragma unroll
    for (int j = 0; j < 16; j++) acc[j] = y0[j];
    const float4* y1 = (const float4*)(g_y + ((size_t)(b * NS) + id.y) * 192 + 64);
    #pragma unroll
    for (int j = 0; j < 16; j++) {
        float4 v = y1[j];
        acc[j].x += v.x; acc[j].y += v.y; acc[j].z += v.z; acc[j].w += v.w;
    }
    const float4* y2 = (const float4*)(g_y + ((size_t)(b * NS) + id.z) * 192 + 128);
    #pragma unroll
    for (int j = 0; j < 16; j++) {
        float4 v = y2[j];
        acc[j].x += v.x; acc[j].y += v.y; acc[j].z += v.z; acc[j].w += v.w;
    }

    int h1 = n >> 6, w1 = n & 63;
    float* ob = out + (size_t)b * C0 * (H0 * W0);
    #pragma unroll
    for (int co = 0; co < 16; co++) {
        *(float2*)(ob + co * (H0 * W0) + (2 * h1)     * W0 + 2 * w1) = make_float2(acc[co].x, acc[co].y);
        *(float2*)(ob + co * (H0 * W0) + (2 * h1 + 1) * W0 + 2 * w1) = make_float2(acc[co].z, acc[co].w);
    }
}

// ---------------- launcher (score_mma in slot 4 so ncu captures it) ----------------
extern "C" void kernel_launch(void* const* d_in, const int* in_sizes, int n_in,
                              void* d_out, int out_size) {
    const float* x    = (const float*)d_in[0];
    const float* w    = (const float*)d_in[1];
    const float* bias = (const float*)d_in[2];
    float* out = (float*)d_out;

    cudaFuncSetAttribute(score_mma_kernel,
                         cudaFuncAttributeMaxDynamicSharedMemorySize, SMEM_MMA);

    unshuffle_kernel<<<B * 64, 256>>>(x);
    sample_kernel<<<B * NS, 64>>>(x);
    wt_kernel<<<48, 256>>>(w);
    score_mma_kernel<<<dim3(NTOK / MT, B), 512, SMEM_MMA>>>();
    rescue_kernel<<<256, 256>>>();
    y_kernel<<<B * NS / 32, 192>>>(bias);
    gather_out_kernel<<<dim3(NTOK / 256, B), 256>>>(out);
}

// round 15
// speedup vs baseline: 5.8417x; 1.0119x over previous
#include <cuda_runtime.h>
#include <cstdint>

// ---------------- problem constants ----------------
#define B      32
#define C0     16
#define H0     128
#define W0     128
#define C1     64
#define NTOK   4096
#define NS     256
#define MT     128          // tokens per MMA CTA
#define THR    3e-4f        // near-tie rescue threshold (~10x worst MMA error)

// ---------------- scratch ----------------
__device__ __align__(16) float  g_xtok[B * NTOK * C1];
__device__ __align__(16) float  g_xs  [B * NS * C1];
__device__ __align__(16) float  g_m2  [B * NS];
__device__ __align__(16) float  g_wt2 [C1 * 3 * C1];
__device__ __align__(16) float  g_y   [B * NS * 3 * C1];
__device__ __align__(16) int4   g_idx [B * NTOK];
__device__ int g_flagcnt;
__device__ int g_flags[B * NTOK];

__device__ const int SAMP[16] = {0,4,8,13,17,21,25,29,34,38,42,46,50,55,59,63};

#define FMA2(a,x,y) asm("fma.rn.f32x2 %0, %1, %2, %0;" : "+l"(a) : "l"(x), "l"(y))
#define UNPK(lo,hi,a) asm("mov.b64 {%0,%1}, %2;" : "=f"(lo), "=f"(hi) : "l"(a))

#define LDSM_X4(r0,r1,r2,r3,addr) \
    asm volatile("ldmatrix.sync.aligned.m8n8.x4.shared.b16 {%0,%1,%2,%3}, [%4];" \
        : "=r"(r0), "=r"(r1), "=r"(r2), "=r"(r3) : "r"(addr))

__device__ __forceinline__ float2 tf32_split(float v) {
    uint32_t hb, lb;
    asm("cvt.rna.tf32.f32 %0, %1;" : "=r"(hb) : "f"(v));
    float hi = __uint_as_float(hb);
    float r = v - hi;
    asm("cvt.rna.tf32.f32 %0, %1;" : "=r"(lb) : "f"(r));
    return make_float2(hi, __uint_as_float(lb));
}

// smem layout (floats)
#define PITCH    132
#define SB_F     0                       // B_ext: 256 x PITCH
#define SA_F     (NS * PITCH)            // A_ext: 128 x PITCH
#define SM2_F    (SA_F + MT * PITCH)     // 256 floats
#define SMEM_F   (SM2_F + NS)
#define SMEM_MMA (SMEM_F * 4)
// post-mainloop reuse: D[128][260] at 0; lists in old A region
#define DRP      260
#define SV2_F    SA_F                    // 512*4 floats
#define SI2_F    (SA_F + 2048)           // 512*4 ints

#define BETTER(s, i, cv, ci) (((s) > (cv)) || ((s) == (cv) && (i) < (ci)))
#define INSERT3(s, idx) do { \
    bool _g0 = BETTER(s, idx, t0, i0), _g1 = BETTER(s, idx, t1, i1), _g2 = BETTER(s, idx, t2, i2); \
    t2 = _g1 ? t1 : (_g2 ? (s) : t2);  i2 = _g1 ? i1 : (_g2 ? (idx) : i2); \
    t1 = _g0 ? t0 : (_g1 ? (s) : t1);  i1 = _g0 ? i0 : (_g1 ? (idx) : i1); \
    t0 = _g0 ? (s) : t0;               i0 = _g0 ? (idx) : i0; \
} while (0)
#define INS4(s, idx) do { \
    bool _g0 = (s) > t0, _g1 = (s) > t1, _g2 = (s) > t2, _g3 = (s) > t3; \
    t3 = _g2 ? t2 : (_g3 ? (s) : t3);  i3 = _g2 ? i2 : (_g3 ? (idx) : i3); \
    t2 = _g1 ? t1 : (_g2 ? (s) : t2);  i2 = _g1 ? i1 : (_g2 ? (idx) : i2); \
    t1 = _g0 ? t0 : (_g1 ? (s) : t1);  i1 = _g0 ? i0 : (_g1 ? (idx) : i1); \
    t0 = _g0 ? (s) : t0;               i0 = _g0 ? (idx) : i0; \
} while (0)

// ---------------- kernel 1: pixel_unshuffle ----------------
__global__ __launch_bounds__(256) void unshuffle_kernel(const float* __restrict__ x) {
    __shared__ __align__(16) float s[128 * 33];
    int b  = blockIdx.x >> 6;
    int h1 = blockIdx.x & 63;
    int t  = threadIdx.x;
    const float* xb = x + (size_t)b * C0 * H0 * W0;
    #pragma unroll
    for (int i = 0; i < 4; i++) {
        int idx = t + 256 * i;
        int r   = idx >> 5;
        int w4  = idx & 31;
        int c = r >> 1, sh = r & 1;
        float4 v = *(const float4*)(xb + ((size_t)c * H0 + (2 * h1 + sh)) * W0 + w4 * 4);
        s[(4 * w4 + 0) * 33 + r] = v.x;
        s[(4 * w4 + 1) * 33 + r] = v.y;
        s[(4 * w4 + 2) * 33 + r] = v.z;
        s[(4 * w4 + 3) * 33 + r] = v.w;
    }
    __syncthreads();
    float* dst = g_xtok + ((size_t)b * NTOK + h1 * 64) * C1;
    #pragma unroll
    for (int i = 0; i < 4; i++) {
        int idx = t + 256 * i;
        int w1 = idx >> 4, q = idx & 15;
        int r0 = (2 * w1) * 33, r1 = (2 * w1 + 1) * 33;
        *(float4*)(dst + idx * 4) = make_float4(
            s[r0 + 2 * q],     s[r1 + 2 * q],
            s[r0 + 2 * q + 1], s[r1 + 2 * q + 1]);
    }
}

// ---------------- kernel 2: sampled tokens + (-0.5*m2) ----------------
__global__ void sample_kernel(const float* __restrict__ x) {
    int pair = blockIdx.x;
    int b = pair >> 8, m = pair & 255;
    int h1 = SAMP[m >> 4], w1 = SAMP[m & 15];
    int c1 = threadIdx.x;
    int c = c1 >> 2, sh = (c1 >> 1) & 1, sw = c1 & 1;
    float v = x[((size_t)(b * C0 + c) * H0 + (2 * h1 + sh)) * W0 + (2 * w1 + sw)];
    g_xs[(size_t)pair * C1 + c1] = v;
    __shared__ float red[64];
    red[c1] = v * v;
    __syncthreads();
    if (c1 < 32) {
        float s = red[c1] + red[c1 + 32];
        #pragma unroll
        for (int off = 16; off; off >>= 1)
            s += __shfl_down_sync(0xffffffffu, s, off);
        if (c1 == 0) g_m2[pair] = -0.5f * s;
    }
}

// ---------------- kernel 3: weight -> [k][o][c] + flag counter reset ----------------
__global__ void wt_kernel(const float* __restrict__ w) {
    int d = blockIdx.x * 256 + threadIdx.x;
    if (d == 0) g_flagcnt = 0;
    int c = d & 63;
    int ko = d >> 6;
    int o = ko & 63, k = ko >> 6;
    g_wt2[d] = w[o * 192 + c * 3 + k];
}

// ---------------- kernel 4 (ncu slot 4): HMMA tf32 GEMM with ldmatrix + scan ---------
__global__ __launch_bounds__(512) void score_mma_kernel() {
    extern __shared__ __align__(16) float sm[];
    float* sA  = sm + SA_F;
    float* sB  = sm + SB_F;
    float* sM2 = sm + SM2_F;
    const int t = threadIdx.x;
    const int w = t >> 5, lane = t & 31;
    const int g = lane >> 2, q = lane & 3;
    const int b = blockIdx.y;
    const int tok0 = blockIdx.x * MT;
    const int nslice = (w & 7) * 32;
    const int mrow0  = (w >> 3) * 64;

    // ---- fill A_ext ----
    const float4* asrc = (const float4*)(g_xtok + ((size_t)b * NTOK + tok0) * C1);
    #pragma unroll
    for (int i = 0; i < 4; i++) {
        int idx = t + 512 * i;
        float4 v = asrc[idx];
        int row = idx >> 4, c0 = (idx & 15) * 4;
        float2 s0 = tf32_split(v.x), s1 = tf32_split(v.y);
        float2 s2 = tf32_split(v.z), s3 = tf32_split(v.w);
        *(float4*)&sA[row * PITCH + c0]      = make_float4(s0.x, s1.x, s2.x, s3.x);
        *(float4*)&sA[row * PITCH + 64 + c0] = make_float4(s0.y, s1.y, s2.y, s3.y);
    }
    // ---- fill B_ext ----
    const float4* bsrc = (const float4*)(g_xs + (size_t)b * NS * C1);
    #pragma unroll
    for (int i = 0; i < 8; i++) {
        int idx = t + 512 * i;
        float4 v = bsrc[idx];
        int row = idx >> 4, c0 = (idx & 15) * 4;
        float2 s0 = tf32_split(v.x), s1 = tf32_split(v.y);
        float2 s2 = tf32_split(v.z), s3 = tf32_split(v.w);
        *(float4*)&sB[row * PITCH + c0]      = make_float4(s0.x, s1.x, s2.x, s3.x);
        *(float4*)&sB[row * PITCH + 64 + c0] = make_float4(s0.y, s1.y, s2.y, s3.y);
    }
    if (t < 256) sM2[t] = g_m2[b * NS + t];
    __syncthreads();

    // ---- ldmatrix lane base addresses (byte, shared space) ----
    const uint32_t sbU = (uint32_t)__cvta_generic_to_shared(sm);
    // A x4 tile: t0 rows0-7/c0, t1 rows8-15/c0, t2 rows0-7/c4, t3 rows8-15/c4
    int aRow = mrow0 + (lane & 7) + ((lane & 8) ? 8 : 0);
    int aCol = (lane & 16) ? 4 : 0;
    uint32_t aBase = sbU + (uint32_t)((SA_F + aRow * PITCH + aCol) * 4);
    // B pair-of-nt x4: t0 nt0/c0, t1 nt0/c4, t2 nt1/c0, t3 nt1/c4
    int bRow = nslice + (((lane >> 4) & 1) + 0) * 8 + (lane & 7);
    int bCol = (lane & 8) ? 4 : 0;
    uint32_t bBase = sbU + (uint32_t)((SB_F + bRow * PITCH + bCol) * 4);

    float c[64];
    #pragma unroll
    for (int i = 0; i < 64; i++) c[i] = 0.f;

    // ---- mainloop: 3 phases (hi*hi, lo*hi, hi*lo) x 8 k-steps ----
    #pragma unroll 1
    for (int ph = 0; ph < 3; ph++) {
        const uint32_t ka = (ph == 1) ? 256u : 0u;   // bytes (64 floats)
        const uint32_t kb = (ph == 2) ? 256u : 0u;
        #pragma unroll 1
        for (int ks = 0; ks < 8; ks++) {
            const uint32_t ko = (uint32_t)(ks * 32);
            uint32_t bf[8];
            LDSM_X4(bf[0], bf[1], bf[2], bf[3], bBase + kb + ko);
            LDSM_X4(bf[4], bf[5], bf[6], bf[7], bBase + 16u * PITCH * 4u + kb + ko);
            #pragma unroll
            for (int mtl = 0; mtl < 4; mtl++) {
                uint32_t a0, a1, a2, a3;
                LDSM_X4(a0, a1, a2, a3, aBase + (uint32_t)(mtl * 16 * PITCH * 4) + ka + ko);
                #pragma unroll
                for (int nt = 0; nt < 4; nt++) {
                    float* cc = &c[(mtl * 4 + nt) * 4];
                    asm volatile(
                        "mma.sync.aligned.m16n8k8.row.col.f32.tf32.tf32.f32 "
                        "{%0,%1,%2,%3}, {%4,%5,%6,%7}, {%8,%9}, {%0,%1,%2,%3};"
                        : "+f"(cc[0]), "+f"(cc[1]), "+f"(cc[2]), "+f"(cc[3])
                        : "r"(a0), "r"(a1), "r"(a2), "r"(a3),
                          "r"(bf[nt * 2]), "r"(bf[nt * 2 + 1]));
                }
            }
        }
    }

    // ---- m2 + adjusted D column (half-pad at 128) ----
    float m2v[8];
    int   colv[4];
    #pragma unroll
    for (int nt = 0; nt < 4; nt++) {
        int col = nslice + nt * 8 + q * 2;
        colv[nt] = col + ((col >= 128) ? 2 : 0);
        m2v[nt * 2]     = sM2[col];
        m2v[nt * 2 + 1] = sM2[col + 1];
    }
    __syncthreads();   // done with sA/sB -> reuse as D + lists

    float* D = sm;
    #pragma unroll
    for (int mtl = 0; mtl < 4; mtl++) {
        #pragma unroll
        for (int half = 0; half < 2; half++) {
            int row = mrow0 + mtl * 16 + g + half * 8;
            #pragma unroll
            for (int nt = 0; nt < 4; nt++) {
                float2 v = make_float2(
                    c[(mtl * 4 + nt) * 4 + half * 2]     + m2v[nt * 2],
                    c[(mtl * 4 + nt) * 4 + half * 2 + 1] + m2v[nt * 2 + 1]);
                *(float2*)&D[row * DRP + colv[nt]] = v;
            }
        }
    }
    __syncthreads();

    // ---- scan: ALL 512 threads, row = t>>2, stride-4 columns (conflict-free) -------
    float* sv2 = sm + SV2_F;
    int*   si2 = (int*)(sm + SI2_F);
    {
        const int row = t >> 2, q4 = t & 3;
        const float* drow = &D[row * DRP];
        float t0 = -3.4e38f, t1 = -3.4e38f, t2 = -3.4e38f, t3 = -3.4e38f;
        int   i0 = 0, i1 = 0, i2 = 0, i3 = 0;
        #pragma unroll
        for (int j = 0; j < 64; j++) {
            int col = q4 + 4 * j;
            float s = drow[col + ((col >= 128) ? 2 : 0)];
            INS4(s, col);
        }
        sv2[t * 4] = t0; sv2[t * 4 + 1] = t1; sv2[t * 4 + 2] = t2; sv2[t * 4 + 3] = t3;
        si2[t * 4] = i0; si2[t * 4 + 1] = i1; si2[t * 4 + 2] = i2; si2[t * 4 + 3] = i3;
    }
    __syncthreads();

    // ---- final: thread t<128 merges its row's four quarter-lists -------------------
    if (t < MT) {
        float t0 = -3.4e38f, t1 = -3.4e38f, t2 = -3.4e38f, t3 = -3.4e38f;
        int   i0 = 0, i1 = 0, i2 = 0, i3 = 0;
        #pragma unroll
        for (int sub = 0; sub < 4; sub++) {
            int ts = t * 4 + sub;
            #pragma unroll
            for (int j = 0; j < 4; j++) INS4(sv2[ts * 4 + j], si2[ts * 4 + j]);
        }
        int tokid = b * NTOK + tok0 + t;
        g_idx[tokid] = make_int4(i0, i1, i2, 0);
        if ((t0 - t1 < THR) || (t1 - t2 < THR) || (t2 - t3 < THR)) {
            int pos = atomicAdd(&g_flagcnt, 1);
            g_flags[pos] = tokid;
        }
    }
}

// ---------------- kernel 5: rescue with R7-bit-identical fp32 arithmetic -------------
__global__ __launch_bounds__(256) void rescue_kernel() {
    int cnt = g_flagcnt;
    if (cnt > B * NTOK) cnt = B * NTOK;
    const int nwarp = (gridDim.x * blockDim.x) >> 5;
    const int wgid  = (blockIdx.x * blockDim.x + threadIdx.x) >> 5;
    const int lane  = threadIdx.x & 31;

    for (int f = wgid; f < cnt; f += nwarp) {
        const int tokid = g_flags[f] & (B * NTOK - 1);
        const int b = tokid >> 12;
        float tv[64];
        const float4* tp = (const float4*)(g_xtok + (size_t)tokid * C1);
        #pragma unroll
        for (int j = 0; j < 16; j++) {
            float4 v = tp[j];
            tv[4 * j] = v.x; tv[4 * j + 1] = v.y; tv[4 * j + 2] = v.z; tv[4 * j + 3] = v.w;
        }
        float t0 = -3.4e38f, t1 = -3.4e38f, t2 = -3.4e38f;
        int   i0 = 0, i1 = 0, i2 = 0;
        #pragma unroll 1
        for (int mi = 0; mi < 8; mi++) {
            int m = mi * 32 + lane;
            const float4* xp = (const float4*)(g_xs + ((size_t)b * NS + m) * C1);
            float c0 = g_m2[b * NS + m];
            float c1 = 0.f, c2 = 0.f, c3 = 0.f, c4 = 0.f, c5 = 0.f, c6 = 0.f, c7 = 0.f;
            #pragma unroll
            for (int j = 0; j < 8; j++) {
                float4 xa = xp[2 * j];
                float4 xb = xp[2 * j + 1];
                c0 = fmaf(tv[8 * j + 0], xa.x, c0);
                c1 = fmaf(tv[8 * j + 1], xa.y, c1);
                c2 = fmaf(tv[8 * j + 2], xa.z, c2);
                c3 = fmaf(tv[8 * j + 3], xa.w, c3);
                c4 = fmaf(tv[8 * j + 4], xb.x, c4);
                c5 = fmaf(tv[8 * j + 5], xb.y, c5);
                c6 = fmaf(tv[8 * j + 6], xb.z, c6);
                c7 = fmaf(tv[8 * j + 7], xb.w, c7);
            }
            float slo = (c0 + c4) + (c2 + c6);
            float shi = (c1 + c5) + (c3 + c7);
            float s = slo + shi;
            INSERT3(s, m);
        }
        #pragma unroll
        for (int dx = 16; dx; dx >>= 1) {
            float o0 = __shfl_xor_sync(~0u, t0, dx), o1 = __shfl_xor_sync(~0u, t1, dx), o2 = __shfl_xor_sync(~0u, t2, dx);
            int   j0 = __shfl_xor_sync(~0u, i0, dx), j1 = __shfl_xor_sync(~0u, i1, dx), j2 = __shfl_xor_sync(~0u, i2, dx);
            INSERT3(o0, j0); INSERT3(o1, j1); INSERT3(o2, j2);
        }
        if (lane == 0) g_idx[tokid] = make_int4(i0, i1, i2, 0);
    }
}

// ---------------- kernel 6: Y[pair][k*64+o] (+bias) ----------------
__global__ __launch_bounds__(192) void y_kernel(const float* __restrict__ bias) {
    int t = threadIdx.x;
    int o = t & 63;
    unsigned long long wq[32];
    const ulonglong2* wp = (const ulonglong2*)(g_wt2 + (size_t)t * 64);
    #pragma unroll
    for (int j = 0; j < 16; j++) { ulonglong2 v = wp[j]; wq[2 * j] = v.x; wq[2 * j + 1] = v.y; }

    __shared__ __align__(16) float s_xs[32 * 64];
    const float4* src = (const float4*)(g_xs + (size_t)blockIdx.x * 32 * 64);
    for (int i = t; i < 512; i += 192) ((float4*)s_xs)[i] = src[i];
    __syncthreads();

    float bo = (t < 64) ? bias[o] : 0.f;
    float* yb = g_y + (size_t)blockIdx.x * 32 * 192;
    #pragma unroll 1
    for (int p0 = 0; p0 < 32; p0 += 8) {
        unsigned long long acc[8] = {0,0,0,0,0,0,0,0};
        #pragma unroll
        for (int jj = 0; jj < 16; jj++) {
            #pragma unroll
            for (int p = 0; p < 8; p++) {
                ulonglong2 xq = *(const ulonglong2*)&s_xs[(p0 + p) * 64 + 4 * jj];
                FMA2(acc[p], wq[2 * jj],     xq.x);
                FMA2(acc[p], wq[2 * jj + 1], xq.y);
            }
        }
        #pragma unroll
        for (int p = 0; p < 8; p++) {
            float lo, hi; UNPK(lo, hi, acc[p]);
            yb[(size_t)(p0 + p) * 192 + t] = lo + hi + bo;
        }
    }
}

// ---------------- kernel 7: gather Y by idx, add, pixel_shuffle write ----------------
__global__ __launch_bounds__(256) void gather_out_kernel(float* __restrict__ out) {
    const int b = blockIdx.y;
    const int n = blockIdx.x * 256 + threadIdx.x;
    int4 id = g_idx[(size_t)b * NTOK + n];

    float4 acc[16];
    const float4* y0 = (const float4*)(g_y + ((size_t)(b * NS) + id.x) * 192);
    #pragma unroll
    for (int j = 0; j < 16; j++) acc[j] = y0[j];
    const float4* y1 = (const float4*)(g_y + ((size_t)(b * NS) + id.y) * 192 + 64);
    #pragma unroll
    for (int j = 0; j < 16; j++) {
        float4 v = y1[j];
        acc[j].x += v.x; acc[j].y += v.y; acc[j].z += v.z; acc[j].w += v.w;
    }
    const float4* y2 = (const float4*)(g_y + ((size_t)(b * NS) + id.z) * 192 + 128);
    #pragma unroll
    for (int j = 0; j < 16; j++) {
        float4 v = y2[j];
        acc[j].x += v.x; acc[j].y += v.y; acc[j].z += v.z; acc[j].w += v.w;
    }

    int h1 = n >> 6, w1 = n & 63;
    float* ob = out + (size_t)b * C0 * (H0 * W0);
    #pragma unroll
    for (int co = 0; co < 16; co++) {
        *(float2*)(ob + co * (H0 * W0) + (2 * h1)     * W0 + 2 * w1) = make_float2(acc[co].x, acc[co].y);
        *(float2*)(ob + co * (H0 * W0) + (2 * h1 + 1) * W0 + 2 * w1) = make_float2(acc[co].z, acc[co].w);
    }
}

// ---------------- launcher ----------------
extern "C" void kernel_launch(void* const* d_in, const int* in_sizes, int n_in,
                              void* d_out, int out_size) {
    const float* x    = (const float*)d_in[0];
    const float* w    = (const float*)d_in[1];
    const float* bias = (const float*)d_in[2];
    float* out = (float*)d_out;

    cudaFuncSetAttribute(score_mma_kernel,
                         cudaFuncAttributeMaxDynamicSharedMemorySize, SMEM_MMA);

    unshuffle_kernel<<<B * 64, 256>>>(x);
    sample_kernel<<<B * NS, 64>>>(x);
    wt_kernel<<<48, 256>>>(w);
    score_mma_kernel<<<dim3(NTOK / MT, B), 512, SMEM_MMA>>>();
    rescue_kernel<<<256, 256>>>();
    y_kernel<<<B * NS / 32, 192>>>(bias);
    gather_out_kernel<<<dim3(NTOK / 256, B), 256>>>(out);
}

// round 16
// speedup vs baseline: 6.3836x; 1.0928x over previous
#include <cuda_runtime.h>
#include <cuda_bf16.h>
#include <cstdint>

// ---------------- problem constants ----------------
#define B      32
#define C0     16
#define H0     128
#define W0     128
#define C1     64
#define NTOK   4096
#define NS     256
#define MT     128          // tokens per MMA CTA
#define THR    5e-4f        // near-tie rescue threshold (~12 sigma of bf16-split error)

// ---------------- scratch ----------------
__device__ __align__(16) float  g_xtok[B * NTOK * C1];
__device__ __align__(16) float  g_xs  [B * NS * C1];
__device__ __align__(16) float  g_m2  [B * NS];
__device__ __align__(16) float  g_wt2 [C1 * 3 * C1];
__device__ __align__(16) float  g_y   [B * NS * 3 * C1];
__device__ __align__(16) int4   g_idx [B * NTOK];
__device__ int g_flagcnt;
__device__ int g_flags[B * NTOK];

__device__ const int SAMP[16] = {0,4,8,13,17,21,25,29,34,38,42,46,50,55,59,63};

#define FMA2(a,x,y) asm("fma.rn.f32x2 %0, %1, %2, %0;" : "+l"(a) : "l"(x), "l"(y))
#define UNPK(lo,hi,a) asm("mov.b64 {%0,%1}, %2;" : "=f"(lo), "=f"(hi) : "l"(a))

#define LDSM_X4(r0,r1,r2,r3,addr) \
    asm volatile("ldmatrix.sync.aligned.m8n8.x4.shared.b16 {%0,%1,%2,%3}, [%4];" \
        : "=r"(r0), "=r"(r1), "=r"(r2), "=r"(r3) : "r"(addr))

#define MMA_BF16(cc,a0,a1,a2,a3,b0,b1) \
    asm volatile("mma.sync.aligned.m16n8k16.row.col.f32.bf16.bf16.f32 " \
        "{%0,%1,%2,%3}, {%4,%5,%6,%7}, {%8,%9}, {%0,%1,%2,%3};" \
        : "+f"((cc)[0]), "+f"((cc)[1]), "+f"((cc)[2]), "+f"((cc)[3]) \
        : "r"(a0), "r"(a1), "r"(a2), "r"(a3), "r"(b0), "r"(b1))

// split float4 into packed hi-bf16x4 (uint2) and mid-bf16x4 (uint2)
__device__ __forceinline__ void bf16_split4(float4 v, uint2& hiw, uint2& midw) {
    __nv_bfloat16 h0 = __float2bfloat16_rn(v.x), h1 = __float2bfloat16_rn(v.y);
    __nv_bfloat16 h2 = __float2bfloat16_rn(v.z), h3 = __float2bfloat16_rn(v.w);
    __nv_bfloat16 m0 = __float2bfloat16_rn(v.x - __bfloat162float(h0));
    __nv_bfloat16 m1 = __float2bfloat16_rn(v.y - __bfloat162float(h1));
    __nv_bfloat16 m2 = __float2bfloat16_rn(v.z - __bfloat162float(h2));
    __nv_bfloat16 m3 = __float2bfloat16_rn(v.w - __bfloat162float(h3));
    hiw.x  = (uint32_t)__bfloat16_as_ushort(h0) | ((uint32_t)__bfloat16_as_ushort(h1) << 16);
    hiw.y  = (uint32_t)__bfloat16_as_ushort(h2) | ((uint32_t)__bfloat16_as_ushort(h3) << 16);
    midw.x = (uint32_t)__bfloat16_as_ushort(m0) | ((uint32_t)__bfloat16_as_ushort(m1) << 16);
    midw.y = (uint32_t)__bfloat16_as_ushort(m2) | ((uint32_t)__bfloat16_as_ushort(m3) << 16);
}

// smem layout (bytes): B bf16 [256][136], A bf16 [128][136], m2 [256]f
#define PITCHH   136                 // bf16 per row (272B; stride%128B=16 -> ldmatrix clean)
#define SB_BYTE  0
#define SA_BYTE  (256 * PITCHH * 2)  // 69632
#define SM2_BYTE (SA_BYTE + 128 * PITCHH * 2)   // 104448
#define SMEM_MMA (SM2_BYTE + 1024)   // 105472
// epilogue reuse (floats over bytes 0..83967; m2 region untouched)
#define DRPH     132                 // D pitch (floats), cols 0..127 per phase
#define SV2_F    16896               // 512*4 floats
#define SI2_F    (16896 + 2048)      // 512*4 ints

#define BETTER(s, i, cv, ci) (((s) > (cv)) || ((s) == (cv) && (i) < (ci)))
#define INSERT3(s, idx) do { \
    bool _g0 = BETTER(s, idx, t0, i0), _g1 = BETTER(s, idx, t1, i1), _g2 = BETTER(s, idx, t2, i2); \
    t2 = _g1 ? t1 : (_g2 ? (s) : t2);  i2 = _g1 ? i1 : (_g2 ? (idx) : i2); \
    t1 = _g0 ? t0 : (_g1 ? (s) : t1);  i1 = _g0 ? i0 : (_g1 ? (idx) : i1); \
    t0 = _g0 ? (s) : t0;               i0 = _g0 ? (idx) : i0; \
} while (0)
#define INS4(s, idx) do { \
    bool _g0 = (s) > t0, _g1 = (s) > t1, _g2 = (s) > t2, _g3 = (s) > t3; \
    t3 = _g2 ? t2 : (_g3 ? (s) : t3);  i3 = _g2 ? i2 : (_g3 ? (idx) : i3); \
    t2 = _g1 ? t1 : (_g2 ? (s) : t2);  i2 = _g1 ? i1 : (_g2 ? (idx) : i2); \
    t1 = _g0 ? t0 : (_g1 ? (s) : t1);  i1 = _g0 ? i0 : (_g1 ? (idx) : i1); \
    t0 = _g0 ? (s) : t0;               i0 = _g0 ? (idx) : i0; \
} while (0)

// ---------------- kernel 1: pixel_unshuffle ----------------
__global__ __launch_bounds__(256) void unshuffle_kernel(const float* __restrict__ x) {
    __shared__ __align__(16) float s[128 * 33];
    int b  = blockIdx.x >> 6;
    int h1 = blockIdx.x & 63;
    int t  = threadIdx.x;
    const float* xb = x + (size_t)b * C0 * H0 * W0;
    #pragma unroll
    for (int i = 0; i < 4; i++) {
        int idx = t + 256 * i;
        int r   = idx >> 5;
        int w4  = idx & 31;
        int c = r >> 1, sh = r & 1;
        float4 v = *(const float4*)(xb + ((size_t)c * H0 + (2 * h1 + sh)) * W0 + w4 * 4);
        s[(4 * w4 + 0) * 33 + r] = v.x;
        s[(4 * w4 + 1) * 33 + r] = v.y;
        s[(4 * w4 + 2) * 33 + r] = v.z;
        s[(4 * w4 + 3) * 33 + r] = v.w;
    }
    __syncthreads();
    float* dst = g_xtok + ((size_t)b * NTOK + h1 * 64) * C1;
    #pragma unroll
    for (int i = 0; i < 4; i++) {
        int idx = t + 256 * i;
        int w1 = idx >> 4, q = idx & 15;
        int r0 = (2 * w1) * 33, r1 = (2 * w1 + 1) * 33;
        *(float4*)(dst + idx * 4) = make_float4(
            s[r0 + 2 * q],     s[r1 + 2 * q],
            s[r0 + 2 * q + 1], s[r1 + 2 * q + 1]);
    }
}

// ---------------- kernel 2: sampled tokens + (-0.5*m2) ----------------
__global__ void sample_kernel(const float* __restrict__ x) {
    int pair = blockIdx.x;
    int b = pair >> 8, m = pair & 255;
    int h1 = SAMP[m >> 4], w1 = SAMP[m & 15];
    int c1 = threadIdx.x;
    int c = c1 >> 2, sh = (c1 >> 1) & 1, sw = c1 & 1;
    float v = x[((size_t)(b * C0 + c) * H0 + (2 * h1 + sh)) * W0 + (2 * w1 + sw)];
    g_xs[(size_t)pair * C1 + c1] = v;
    __shared__ float red[64];
    red[c1] = v * v;
    __syncthreads();
    if (c1 < 32) {
        float s = red[c1] + red[c1 + 32];
        #pragma unroll
        for (int off = 16; off; off >>= 1)
            s += __shfl_down_sync(0xffffffffu, s, off);
        if (c1 == 0) g_m2[pair] = -0.5f * s;
    }
}

// ---------------- kernel 3: weight -> [k][o][c] + flag counter reset ----------------
__global__ void wt_kernel(const float* __restrict__ w) {
    int d = blockIdx.x * 256 + threadIdx.x;
    if (d == 0) g_flagcnt = 0;
    int c = d & 63;
    int ko = d >> 6;
    int o = ko & 63, k = ko >> 6;
    g_wt2[d] = w[o * 192 + c * 3 + k];
}

// ---------------- kernel 4 (ncu slot 4): bf16 2-pass HMMA GEMM + two-phase scan ------
// v = hi + mid (bf16 each). pass0: A(hi|mid)·B(hi|mid) = hh+mm.
// pass1: B columns rotated by 64 -> hm+mh. Sum = (hi+mid)A·(hi+mid)B.
__global__ __launch_bounds__(512) void score_mma_kernel() {
    extern __shared__ __align__(16) char smraw[];
    float* sM2 = (float*)(smraw + SM2_BYTE);
    float* smf = (float*)smraw;
    const int t = threadIdx.x;
    const int w = t >> 5, lane = t & 31;
    const int g = lane >> 2, q = lane & 3;
    const int b = blockIdx.y;
    const int tok0 = blockIdx.x * MT;
    const int nslice = (w & 7) * 32;
    const int mrow0  = (w >> 3) * 64;

    // ---- fill A (hi cols 0..63, mid cols 64..127) ----
    const float4* asrc = (const float4*)(g_xtok + ((size_t)b * NTOK + tok0) * C1);
    #pragma unroll
    for (int i = 0; i < 4; i++) {
        int idx = t + 512 * i;               // 0..2047
        float4 v = asrc[idx];
        int row = idx >> 4, c0 = (idx & 15) * 4;
        uint2 hiw, midw;
        bf16_split4(v, hiw, midw);
        *(uint2*)(smraw + SA_BYTE + (row * PITCHH + c0) * 2)        = hiw;
        *(uint2*)(smraw + SA_BYTE + (row * PITCHH + 64 + c0) * 2)   = midw;
    }
    // ---- fill B ----
    const float4* bsrc = (const float4*)(g_xs + (size_t)b * NS * C1);
    #pragma unroll
    for (int i = 0; i < 8; i++) {
        int idx = t + 512 * i;               // 0..4095
        float4 v = bsrc[idx];
        int row = idx >> 4, c0 = (idx & 15) * 4;
        uint2 hiw, midw;
        bf16_split4(v, hiw, midw);
        *(uint2*)(smraw + SB_BYTE + (row * PITCHH + c0) * 2)        = hiw;
        *(uint2*)(smraw + SB_BYTE + (row * PITCHH + 64 + c0) * 2)   = midw;
    }
    if (t < 256) sM2[t] = g_m2[b * NS + t];
    __syncthreads();

    // ---- ldmatrix lane base addresses ----
    const uint32_t sbU = (uint32_t)__cvta_generic_to_shared(smraw);
    int aRow = mrow0 + (lane & 7) + ((lane & 8) ? 8 : 0);
    uint32_t aBase = sbU + SA_BYTE + (uint32_t)(aRow * (PITCHH * 2)) + ((lane & 16) ? 16u : 0u);
    int bRow = nslice + ((lane >> 4) & 1) * 8 + (lane & 7);
    uint32_t bBase = sbU + SB_BYTE + (uint32_t)(bRow * (PITCHH * 2)) + ((lane & 8) ? 16u : 0u);

    float c[64];
    #pragma unroll
    for (int i = 0; i < 64; i++) c[i] = 0.f;

    // ---- mainloop: 2 passes x 8 k-steps (K=16 bf16 each) ----
    #pragma unroll 1
    for (int pass = 0; pass < 2; pass++) {
        #pragma unroll 1
        for (int j = 0; j < 8; j++) {
            const uint32_t koA = (uint32_t)(j * 32);                       // bytes
            const uint32_t koB = (uint32_t)(((16 * j + 64 * pass) & 127) * 2);
            uint32_t bf[8];
            LDSM_X4(bf[0], bf[1], bf[2], bf[3], bBase + koB);
            LDSM_X4(bf[4], bf[5], bf[6], bf[7], bBase + 16u * (PITCHH * 2) + koB);
            #pragma unroll
            for (int mtl = 0; mtl < 4; mtl++) {
                uint32_t a0, a1, a2, a3;
                LDSM_X4(a0, a1, a2, a3, aBase + (uint32_t)(mtl * 16 * (PITCHH * 2)) + koA);
                #pragma unroll
                for (int nt = 0; nt < 4; nt++)
                    MMA_BF16(&c[(mtl * 4 + nt) * 4], a0, a1, a2, a3, bf[nt * 2], bf[nt * 2 + 1]);
            }
        }
    }

    // ---- m2 per owned column ----
    float m2v[8];
    int   colv[4];
    #pragma unroll
    for (int nt = 0; nt < 4; nt++) {
        int col = nslice + nt * 8 + q * 2;
        colv[nt] = col & 127;                // local col within phase
        m2v[nt * 2]     = sM2[col];
        m2v[nt * 2 + 1] = sM2[col + 1];
    }
    __syncthreads();   // done with A/B bf16 -> reuse as D + lists

    float* D = smf;    // [128][DRPH] floats, one 128-col phase at a time
    float t0 = -3.4e38f, t1 = -3.4e38f, t2 = -3.4e38f, t3 = -3.4e38f;
    int   i0 = 0, i1 = 0, i2 = 0, i3 = 0;
    const int scanRow = t >> 2, q4 = t & 3;

    #pragma unroll
    for (int phase = 0; phase < 2; phase++) {
        // warps owning this half write their scores
        if ((w & 7) / 4 == phase) {
            #pragma unroll
            for (int mtl = 0; mtl < 4; mtl++) {
                #pragma unroll
                for (int half = 0; half < 2; half++) {
                    int row = mrow0 + mtl * 16 + g + half * 8;
                    #pragma unroll
                    for (int nt = 0; nt < 4; nt++) {
                        float2 v = make_float2(
                            c[(mtl * 4 + nt) * 4 + half * 2]     + m2v[nt * 2],
                            c[(mtl * 4 + nt) * 4 + half * 2 + 1] + m2v[nt * 2 + 1]);
                        *(float2*)&D[row * DRPH + colv[nt]] = v;
                    }
                }
            }
        }
        __syncthreads();
        // all 512 threads scan: row = t>>2, stride-4 cols (conflict-free)
        const float* drow = &D[scanRow * DRPH];
        const int ib = phase * 128;
        #pragma unroll
        for (int j = 0; j < 32; j++) {
            int col = q4 + 4 * j;
            INS4(drow[col], ib + col);
        }
        __syncthreads();
    }

    // store quarter-lists
    float* sv2 = smf + SV2_F;
    int*   si2 = (int*)(smf + SI2_F);
    sv2[t * 4] = t0; sv2[t * 4 + 1] = t1; sv2[t * 4 + 2] = t2; sv2[t * 4 + 3] = t3;
    si2[t * 4] = i0; si2[t * 4 + 1] = i1; si2[t * 4 + 2] = i2; si2[t * 4 + 3] = i3;
    __syncthreads();

    // final: thread t<128 merges its row's four quarter-lists
    if (t < MT) {
        float u0 = -3.4e38f, u1 = -3.4e38f, u2 = -3.4e38f, u3 = -3.4e38f;
        int   j0 = 0, j1 = 0, j2 = 0, j3 = 0;
        #pragma unroll
        for (int sub = 0; sub < 4; sub++) {
            int ts = t * 4 + sub;
            #pragma unroll
            for (int j = 0; j < 4; j++) {
                float s = sv2[ts * 4 + j]; int idx = si2[ts * 4 + j];
                bool g0 = s > u0, g1 = s > u1, g2 = s > u2, g3 = s > u3;
                u3 = g2 ? u2 : (g3 ? s : u3);  j3 = g2 ? j2 : (g3 ? idx : j3);
                u2 = g1 ? u1 : (g2 ? s : u2);  j2 = g1 ? j1 : (g2 ? idx : j2);
                u1 = g0 ? u0 : (g1 ? s : u1);  j1 = g0 ? j0 : (g1 ? idx : j1);
                u0 = g0 ? s  : u0;             j0 = g0 ? idx : j0;
            }
        }
        int tokid = b * NTOK + tok0 + t;
        g_idx[tokid] = make_int4(j0, j1, j2, 0);
        if ((u0 - u1 < THR) || (u1 - u2 < THR) || (u2 - u3 < THR)) {
            int pos = atomicAdd(&g_flagcnt, 1);
            g_flags[pos] = tokid;
        }
    }
}

// ---------------- kernel 5: rescue with R7-bit-identical fp32 arithmetic -------------
__global__ __launch_bounds__(256) void rescue_kernel() {
    int cnt = g_flagcnt;
    if (cnt > B * NTOK) cnt = B * NTOK;
    const int nwarp = (gridDim.x * blockDim.x) >> 5;
    const int wgid  = (blockIdx.x * blockDim.x + threadIdx.x) >> 5;
    const int lane  = threadIdx.x & 31;

    for (int f = wgid; f < cnt; f += nwarp) {
        const int tokid = g_flags[f] & (B * NTOK - 1);
        const int b = tokid >> 12;
        float tv[64];
        const float4* tp = (const float4*)(g_xtok + (size_t)tokid * C1);
        #pragma unroll
        for (int j = 0; j < 16; j++) {
            float4 v = tp[j];
            tv[4 * j] = v.x; tv[4 * j + 1] = v.y; tv[4 * j + 2] = v.z; tv[4 * j + 3] = v.w;
        }
        float t0 = -3.4e38f, t1 = -3.4e38f, t2 = -3.4e38f;
        int   i0 = 0, i1 = 0, i2 = 0;
        #pragma unroll 1
        for (int mi = 0; mi < 8; mi++) {
            int m = mi * 32 + lane;
            const float4* xp = (const float4*)(g_xs + ((size_t)b * NS + m) * C1);
            float c0 = g_m2[b * NS + m];
            float c1 = 0.f, c2 = 0.f, c3 = 0.f, c4 = 0.f, c5 = 0.f, c6 = 0.f, c7 = 0.f;
            #pragma unroll
            for (int j = 0; j < 8; j++) {
                float4 xa = xp[2 * j];
                float4 xb = xp[2 * j + 1];
                c0 = fmaf(tv[8 * j + 0], xa.x, c0);
                c1 = fmaf(tv[8 * j + 1], xa.y, c1);
                c2 = fmaf(tv[8 * j + 2], xa.z, c2);
                c3 = fmaf(tv[8 * j + 3], xa.w, c3);
                c4 = fmaf(tv[8 * j + 4], xb.x, c4);
                c5 = fmaf(tv[8 * j + 5], xb.y, c5);
                c6 = fmaf(tv[8 * j + 6], xb.z, c6);
                c7 = fmaf(tv[8 * j + 7], xb.w, c7);
            }
            float slo = (c0 + c4) + (c2 + c6);
            float shi = (c1 + c5) + (c3 + c7);
            float s = slo + shi;
            INSERT3(s, m);
        }
        #pragma unroll
        for (int dx = 16; dx; dx >>= 1) {
            float o0 = __shfl_xor_sync(~0u, t0, dx), o1 = __shfl_xor_sync(~0u, t1, dx), o2 = __shfl_xor_sync(~0u, t2, dx);
            int   j0 = __shfl_xor_sync(~0u, i0, dx), j1 = __shfl_xor_sync(~0u, i1, dx), j2 = __shfl_xor_sync(~0u, i2, dx);
            INSERT3(o0, j0); INSERT3(o1, j1); INSERT3(o2, j2);
        }
        if (lane == 0) g_idx[tokid] = make_int4(i0, i1, i2, 0);
    }
}

// ---------------- kernel 6: Y[pair][k*64+o] (+bias) ----------------
__global__ __launch_bounds__(192) void y_kernel(const float* __restrict__ bias) {
    int t = threadIdx.x;
    int o = t & 63;
    unsigned long long wq[32];
    const ulonglong2* wp = (const ulonglong2*)(g_wt2 + (size_t)t * 64);
    #pragma unroll
    for (int j = 0; j < 16; j++) { ulonglong2 v = wp[j]; wq[2 * j] = v.x; wq[2 * j + 1] = v.y; }

    __shared__ __align__(16) float s_xs[32 * 64];
    const float4* src = (const float4*)(g_xs + (size_t)blockIdx.x * 32 * 64);
    for (int i = t; i < 512; i += 192) ((float4*)s_xs)[i] = src[i];
    __syncthreads();

    float bo = (t < 64) ? bias[o] : 0.f;
    float* yb = g_y + (size_t)blockIdx.x * 32 * 192;
    #pragma unroll 1
    for (int p0 = 0; p0 < 32; p0 += 8) {
        unsigned long long acc[8] = {0,0,0,0,0,0,0,0};
        #pragma unroll
        for (int jj = 0; jj < 16; jj++) {
            #pragma unroll
            for (int p = 0; p < 8; p++) {
                ulonglong2 xq = *(const ulonglong2*)&s_xs[(p0 + p) * 64 + 4 * jj];
                FMA2(acc[p], wq[2 * jj],     xq.x);
                FMA2(acc[p], wq[2 * jj + 1], xq.y);
            }
        }
        #pragma unroll
        for (int p = 0; p < 8; p++) {
            float lo, hi; UNPK(lo, hi, acc[p]);
            yb[(size_t)(p0 + p) * 192 + t] = lo + hi + bo;
        }
    }
}

// ---------------- kernel 7: gather Y by idx, add, pixel_shuffle write ----------------
__global__ __launch_bounds__(256) void gather_out_kernel(float* __restrict__ out) {
    const int b = blockIdx.y;
    const int n = blockIdx.x * 256 + threadIdx.x;
    int4 id = g_idx[(size_t)b * NTOK + n];

    float4 acc[16];
    const float4* y0 = (const float4*)(g_y + ((size_t)(b * NS) + id.x) * 192);
    #pragma unroll
    for (int j = 0; j < 16; j++) acc[j] = y0[j];
    const float4* y1 = (const float4*)(g_y + ((size_t)(b * NS) + id.y) * 192 + 64);
    #pragma unroll
    for (int j = 0; j < 16; j++) {
        float4 v = y1[j];
        acc[j].x += v.x; acc[j].y += v.y; acc[j].z += v.z; acc[j].w += v.w;
    }
    const float4* y2 = (const float4*)(g_y + ((size_t)(b * NS) + id.z) * 192 + 128);
    #pragma unroll
    for (int j = 0; j < 16; j++) {
        float4 v = y2[j];
        acc[j].x += v.x; acc[j].y += v.y; acc[j].z += v.z; acc[j].w += v.w;
    }

    int h1 = n >> 6, w1 = n & 63;
    float* ob = out + (size_t)b * C0 * (H0 * W0);
    #pragma unroll
    for (int co = 0; co < 16; co++) {
        *(float2*)(ob + co * (H0 * W0) + (2 * h1)     * W0 + 2 * w1) = make_float2(acc[co].x, acc[co].y);
        *(float2*)(ob + co * (H0 * W0) + (2 * h1 + 1) * W0 + 2 * w1) = make_float2(acc[co].z, acc[co].w);
    }
}

// ---------------- launcher (score_mma in slot 4 so ncu captures it) ----------------
extern "C" void kernel_launch(void* const* d_in, const int* in_sizes, int n_in,
                              void* d_out, int out_size) {
    const float* x    = (const float*)d_in[0];
    const float* w    = (const float*)d_in[1];
    const float* bias = (const float*)d_in[2];
    float* out = (float*)d_out;

    cudaFuncSetAttribute(score_mma_kernel,
                         cudaFuncAttributeMaxDynamicSharedMemorySize, SMEM_MMA);

    unshuffle_kernel<<<B * 64, 256>>>(x);
    sample_kernel<<<B * NS, 64>>>(x);
    wt_kernel<<<48, 256>>>(w);
    score_mma_kernel<<<dim3(NTOK / MT, B), 512, SMEM_MMA>>>();
    rescue_kernel<<<256, 256>>>();
    y_kernel<<<B * NS / 32, 192>>>(bias);
    gather_out_kernel<<<dim3(NTOK / 256, B), 256>>>(out);
}

// round 17
// speedup vs baseline: 6.7856x; 1.0630x over previous
#include <cuda_runtime.h>
#include <cuda_bf16.h>
#include <cstdint>

// ---------------- problem constants ----------------
#define B      32
#define C0     16
#define H0     128
#define W0     128
#define C1     64
#define NTOK   4096
#define NS     256
#define MT     128          // tokens per MMA CTA
#define THR    5e-4f        // near-tie rescue threshold (~12 sigma of bf16-split error)

// ---------------- scratch ----------------
__device__ __align__(16) float  g_xtok[B * NTOK * C1];
__device__ __align__(16) float  g_xs  [B * NS * C1];
__device__ __align__(16) float  g_m2  [B * NS];
__device__ __align__(16) float  g_wt2 [C1 * 3 * C1];
__device__ __align__(16) float  g_y   [B * NS * 3 * C1];
__device__ int g_flagcnt;
__device__ int g_flags[B * NTOK];

__device__ const int SAMP[16] = {0,4,8,13,17,21,25,29,34,38,42,46,50,55,59,63};

#define FMA2(a,x,y) asm("fma.rn.f32x2 %0, %1, %2, %0;" : "+l"(a) : "l"(x), "l"(y))
#define UNPK(lo,hi,a) asm("mov.b64 {%0,%1}, %2;" : "=f"(lo), "=f"(hi) : "l"(a))

#define LDSM_X4(r0,r1,r2,r3,addr) \
    asm volatile("ldmatrix.sync.aligned.m8n8.x4.shared.b16 {%0,%1,%2,%3}, [%4];" \
        : "=r"(r0), "=r"(r1), "=r"(r2), "=r"(r3) : "r"(addr))

#define MMA_BF16(cc,a0,a1,a2,a3,b0,b1) \
    asm volatile("mma.sync.aligned.m16n8k16.row.col.f32.bf16.bf16.f32 " \
        "{%0,%1,%2,%3}, {%4,%5,%6,%7}, {%8,%9}, {%0,%1,%2,%3};" \
        : "+f"((cc)[0]), "+f"((cc)[1]), "+f"((cc)[2]), "+f"((cc)[3]) \
        : "r"(a0), "r"(a1), "r"(a2), "r"(a3), "r"(b0), "r"(b1))

__device__ __forceinline__ void bf16_split4(float4 v, uint2& hiw, uint2& midw) {
    __nv_bfloat16 h0 = __float2bfloat16_rn(v.x), h1 = __float2bfloat16_rn(v.y);
    __nv_bfloat16 h2 = __float2bfloat16_rn(v.z), h3 = __float2bfloat16_rn(v.w);
    __nv_bfloat16 m0 = __float2bfloat16_rn(v.x - __bfloat162float(h0));
    __nv_bfloat16 m1 = __float2bfloat16_rn(v.y - __bfloat162float(h1));
    __nv_bfloat16 m2 = __float2bfloat16_rn(v.z - __bfloat162float(h2));
    __nv_bfloat16 m3 = __float2bfloat16_rn(v.w - __bfloat162float(h3));
    hiw.x  = (uint32_t)__bfloat16_as_ushort(h0) | ((uint32_t)__bfloat16_as_ushort(h1) << 16);
    hiw.y  = (uint32_t)__bfloat16_as_ushort(h2) | ((uint32_t)__bfloat16_as_ushort(h3) << 16);
    midw.x = (uint32_t)__bfloat16_as_ushort(m0) | ((uint32_t)__bfloat16_as_ushort(m1) << 16);
    midw.y = (uint32_t)__bfloat16_as_ushort(m2) | ((uint32_t)__bfloat16_as_ushort(m3) << 16);
}

// smem layout (bytes): B bf16 [256][136], A bf16 [128][136], m2 [256]f
#define PITCHH   136
#define SB_BYTE  0
#define SA_BYTE  (256 * PITCHH * 2)             // 69632
#define SM2_BYTE (SA_BYTE + 128 * PITCHH * 2)   // 104448
#define SMEM_MMA (SM2_BYTE + 1024)              // 105472
// epilogue reuse (float indices into smf): D [128][132] at 0; lists above it
#define DRPH     132
#define SV2_F    16896               // 512*4 floats
#define SI2_F    (16896 + 2048)      // 512*4 ints
#define SIDX_F   (16896 + 4096)      // 128 int4

#define BETTER(s, i, cv, ci) (((s) > (cv)) || ((s) == (cv) && (i) < (ci)))
#define INSERT3(s, idx) do { \
    bool _g0 = BETTER(s, idx, t0, i0), _g1 = BETTER(s, idx, t1, i1), _g2 = BETTER(s, idx, t2, i2); \
    t2 = _g1 ? t1 : (_g2 ? (s) : t2);  i2 = _g1 ? i1 : (_g2 ? (idx) : i2); \
    t1 = _g0 ? t0 : (_g1 ? (s) : t1);  i1 = _g0 ? i0 : (_g1 ? (idx) : i1); \
    t0 = _g0 ? (s) : t0;               i0 = _g0 ? (idx) : i0; \
} while (0)
#define INS4(s, idx) do { \
    bool _g0 = (s) > t0, _g1 = (s) > t1, _g2 = (s) > t2, _g3 = (s) > t3; \
    t3 = _g2 ? t2 : (_g3 ? (s) : t3);  i3 = _g2 ? i2 : (_g3 ? (idx) : i3); \
    t2 = _g1 ? t1 : (_g2 ? (s) : t2);  i2 = _g1 ? i1 : (_g2 ? (idx) : i2); \
    t1 = _g0 ? t0 : (_g1 ? (s) : t1);  i1 = _g0 ? i0 : (_g1 ? (idx) : i1); \
    t0 = _g0 ? (s) : t0;               i0 = _g0 ? (idx) : i0; \
} while (0)

// ---------------- kernel 1: pixel_unshuffle ----------------
__global__ __launch_bounds__(256) void unshuffle_kernel(const float* __restrict__ x) {
    __shared__ __align__(16) float s[128 * 33];
    int b  = blockIdx.x >> 6;
    int h1 = blockIdx.x & 63;
    int t  = threadIdx.x;
    const float* xb = x + (size_t)b * C0 * H0 * W0;
    #pragma unroll
    for (int i = 0; i < 4; i++) {
        int idx = t + 256 * i;
        int r   = idx >> 5;
        int w4  = idx & 31;
        int c = r >> 1, sh = r & 1;
        float4 v = *(const float4*)(xb + ((size_t)c * H0 + (2 * h1 + sh)) * W0 + w4 * 4);
        s[(4 * w4 + 0) * 33 + r] = v.x;
        s[(4 * w4 + 1) * 33 + r] = v.y;
        s[(4 * w4 + 2) * 33 + r] = v.z;
        s[(4 * w4 + 3) * 33 + r] = v.w;
    }
    __syncthreads();
    float* dst = g_xtok + ((size_t)b * NTOK + h1 * 64) * C1;
    #pragma unroll
    for (int i = 0; i < 4; i++) {
        int idx = t + 256 * i;
        int w1 = idx >> 4, q = idx & 15;
        int r0 = (2 * w1) * 33, r1 = (2 * w1 + 1) * 33;
        *(float4*)(dst + idx * 4) = make_float4(
            s[r0 + 2 * q],     s[r1 + 2 * q],
            s[r0 + 2 * q + 1], s[r1 + 2 * q + 1]);
    }
}

// ---------------- kernel 2: sampled tokens + (-0.5*m2) + wt transpose + flag reset ---
__global__ void sample_kernel(const float* __restrict__ x, const float* __restrict__ w) {
    int pair = blockIdx.x;
    if (pair >= B * NS) {                       // tail blocks: weight transpose
        int d = (pair - B * NS) * 64 + threadIdx.x;   // < 12288
        if (d == 0) g_flagcnt = 0;
        int c = d & 63;
        int ko = d >> 6;
        int o = ko & 63, k = ko >> 6;
        g_wt2[d] = w[o * 192 + c * 3 + k];
        return;
    }
    int b = pair >> 8, m = pair & 255;
    int h1 = SAMP[m >> 4], w1 = SAMP[m & 15];
    int c1 = threadIdx.x;
    int c = c1 >> 2, sh = (c1 >> 1) & 1, sw = c1 & 1;
    float v = x[((size_t)(b * C0 + c) * H0 + (2 * h1 + sh)) * W0 + (2 * w1 + sw)];
    g_xs[(size_t)pair * C1 + c1] = v;
    __shared__ float red[64];
    red[c1] = v * v;
    __syncthreads();
    if (c1 < 32) {
        float s = red[c1] + red[c1 + 32];
        #pragma unroll
        for (int off = 16; off; off >>= 1)
            s += __shfl_down_sync(0xffffffffu, s, off);
        if (c1 == 0) g_m2[pair] = -0.5f * s;
    }
}

// ---------------- kernel 3: Y[pair][k*64+o] (+bias) ----------------
__global__ __launch_bounds__(192) void y_kernel(const float* __restrict__ bias) {
    int t = threadIdx.x;
    int o = t & 63;
    unsigned long long wq[32];
    const ulonglong2* wp = (const ulonglong2*)(g_wt2 + (size_t)t * 64);
    #pragma unroll
    for (int j = 0; j < 16; j++) { ulonglong2 v = wp[j]; wq[2 * j] = v.x; wq[2 * j + 1] = v.y; }

    __shared__ __align__(16) float s_xs[32 * 64];
    const float4* src = (const float4*)(g_xs + (size_t)blockIdx.x * 32 * 64);
    for (int i = t; i < 512; i += 192) ((float4*)s_xs)[i] = src[i];
    __syncthreads();

    float bo = (t < 64) ? bias[o] : 0.f;
    float* yb = g_y + (size_t)blockIdx.x * 32 * 192;
    #pragma unroll 1
    for (int p0 = 0; p0 < 32; p0 += 8) {
        unsigned long long acc[8] = {0,0,0,0,0,0,0,0};
        #pragma unroll
        for (int jj = 0; jj < 16; jj++) {
            #pragma unroll
            for (int p = 0; p < 8; p++) {
                ulonglong2 xq = *(const ulonglong2*)&s_xs[(p0 + p) * 64 + 4 * jj];
                FMA2(acc[p], wq[2 * jj],     xq.x);
                FMA2(acc[p], wq[2 * jj + 1], xq.y);
            }
        }
        #pragma unroll
        for (int p = 0; p < 8; p++) {
            float lo, hi; UNPK(lo, hi, acc[p]);
            yb[(size_t)(p0 + p) * 192 + t] = lo + hi + bo;
        }
    }
}

// ---------------- kernel 4 (ncu slot 4): bf16 2-pass HMMA + top-4 + FUSED gather -----
__global__ __launch_bounds__(512) void score_mma_kernel(float* __restrict__ out) {
    extern __shared__ __align__(16) char smraw[];
    float* sM2 = (float*)(smraw + SM2_BYTE);
    float* smf = (float*)smraw;
    const int t = threadIdx.x;
    const int w = t >> 5, lane = t & 31;
    const int g = lane >> 2, q = lane & 3;
    const int b = blockIdx.y;
    const int tok0 = blockIdx.x * MT;
    const int nslice = (w & 7) * 32;
    const int mrow0  = (w >> 3) * 64;

    // ---- fill A (hi cols 0..63, mid cols 64..127) ----
    const float4* asrc = (const float4*)(g_xtok + ((size_t)b * NTOK + tok0) * C1);
    #pragma unroll
    for (int i = 0; i < 4; i++) {
        int idx = t + 512 * i;
        float4 v = asrc[idx];
        int row = idx >> 4, c0 = (idx & 15) * 4;
        uint2 hiw, midw;
        bf16_split4(v, hiw, midw);
        *(uint2*)(smraw + SA_BYTE + (row * PITCHH + c0) * 2)      = hiw;
        *(uint2*)(smraw + SA_BYTE + (row * PITCHH + 64 + c0) * 2) = midw;
    }
    // ---- fill B ----
    const float4* bsrc = (const float4*)(g_xs + (size_t)b * NS * C1);
    #pragma unroll
    for (int i = 0; i < 8; i++) {
        int idx = t + 512 * i;
        float4 v = bsrc[idx];
        int row = idx >> 4, c0 = (idx & 15) * 4;
        uint2 hiw, midw;
        bf16_split4(v, hiw, midw);
        *(uint2*)(smraw + SB_BYTE + (row * PITCHH + c0) * 2)      = hiw;
        *(uint2*)(smraw + SB_BYTE + (row * PITCHH + 64 + c0) * 2) = midw;
    }
    if (t < 256) sM2[t] = g_m2[b * NS + t];
    __syncthreads();

    const uint32_t sbU = (uint32_t)__cvta_generic_to_shared(smraw);
    int aRow = mrow0 + (lane & 7) + ((lane & 8) ? 8 : 0);
    uint32_t aBase = sbU + SA_BYTE + (uint32_t)(aRow * (PITCHH * 2)) + ((lane & 16) ? 16u : 0u);
    int bRow = nslice + ((lane >> 4) & 1) * 8 + (lane & 7);
    uint32_t bBase = sbU + SB_BYTE + (uint32_t)(bRow * (PITCHH * 2)) + ((lane & 8) ? 16u : 0u);

    float c[64];
    #pragma unroll
    for (int i = 0; i < 64; i++) c[i] = 0.f;

    // ---- mainloop: 2 passes x 8 k-steps, unroll 2 so ptxas pipelines LDSM/MMA ----
    #pragma unroll 1
    for (int pass = 0; pass < 2; pass++) {
        #pragma unroll 2
        for (int j = 0; j < 8; j++) {
            const uint32_t koA = (uint32_t)(j * 32);
            const uint32_t koB = (uint32_t)(((16 * j + 64 * pass) & 127) * 2);
            uint32_t bf[8];
            LDSM_X4(bf[0], bf[1], bf[2], bf[3], bBase + koB);
            LDSM_X4(bf[4], bf[5], bf[6], bf[7], bBase + 16u * (PITCHH * 2) + koB);
            #pragma unroll
            for (int mtl = 0; mtl < 4; mtl++) {
                uint32_t a0, a1, a2, a3;
                LDSM_X4(a0, a1, a2, a3, aBase + (uint32_t)(mtl * 16 * (PITCHH * 2)) + koA);
                #pragma unroll
                for (int nt = 0; nt < 4; nt++)
                    MMA_BF16(&c[(mtl * 4 + nt) * 4], a0, a1, a2, a3, bf[nt * 2], bf[nt * 2 + 1]);
            }
        }
    }

    // ---- m2 per owned column ----
    float m2v[8];
    int   colv[4];
    #pragma unroll
    for (int nt = 0; nt < 4; nt++) {
        int col = nslice + nt * 8 + q * 2;
        colv[nt] = col & 127;
        m2v[nt * 2]     = sM2[col];
        m2v[nt * 2 + 1] = sM2[col + 1];
    }
    __syncthreads();

    float* D = smf;
    float t0 = -3.4e38f, t1 = -3.4e38f, t2 = -3.4e38f, t3 = -3.4e38f;
    int   i0 = 0, i1 = 0, i2 = 0, i3 = 0;
    const int scanRow = t >> 2, q4 = t & 3;

    #pragma unroll
    for (int phase = 0; phase < 2; phase++) {
        if ((w & 7) / 4 == phase) {
            #pragma unroll
            for (int mtl = 0; mtl < 4; mtl++) {
                #pragma unroll
                for (int half = 0; half < 2; half++) {
                    int row = mrow0 + mtl * 16 + g + half * 8;
                    #pragma unroll
                    for (int nt = 0; nt < 4; nt++) {
                        float2 v = make_float2(
                            c[(mtl * 4 + nt) * 4 + half * 2]     + m2v[nt * 2],
                            c[(mtl * 4 + nt) * 4 + half * 2 + 1] + m2v[nt * 2 + 1]);
                        *(float2*)&D[row * DRPH + colv[nt]] = v;
                    }
                }
            }
        }
        __syncthreads();
        const float* drow = &D[scanRow * DRPH];
        const int ib = phase * 128;
        #pragma unroll
        for (int j = 0; j < 32; j++) {
            int col = q4 + 4 * j;
            INS4(drow[col], ib + col);
        }
        __syncthreads();
    }

    float* sv2 = smf + SV2_F;
    int*   si2 = (int*)(smf + SI2_F);
    sv2[t * 4] = t0; sv2[t * 4 + 1] = t1; sv2[t * 4 + 2] = t2; sv2[t * 4 + 3] = t3;
    si2[t * 4] = i0; si2[t * 4 + 1] = i1; si2[t * 4 + 2] = i2; si2[t * 4 + 3] = i3;
    __syncthreads();

    // ---- final merge per token (t<128), flag near-ties, stash idx in smem ----
    int4* sidx = (int4*)(smf + SIDX_F);
    if (t < MT) {
        float u0 = -3.4e38f, u1 = -3.4e38f, u2 = -3.4e38f, u3 = -3.4e38f;
        int   j0 = 0, j1 = 0, j2 = 0, j3 = 0;
        #pragma unroll
        for (int sub = 0; sub < 4; sub++) {
            int ts = t * 4 + sub;
            #pragma unroll
            for (int j = 0; j < 4; j++) {
                float s = sv2[ts * 4 + j]; int idx = si2[ts * 4 + j];
                bool g0 = s > u0, g1 = s > u1, g2 = s > u2, g3 = s > u3;
                u3 = g2 ? u2 : (g3 ? s : u3);  j3 = g2 ? j2 : (g3 ? idx : j3);
                u2 = g1 ? u1 : (g2 ? s : u2);  j2 = g1 ? j1 : (g2 ? idx : j2);
                u1 = g0 ? u0 : (g1 ? s : u1);  j1 = g0 ? j0 : (g1 ? idx : j1);
                u0 = g0 ? s  : u0;             j0 = g0 ? idx : j0;
            }
        }
        sidx[t] = make_int4(j0, j1, j2, 0);
        if ((u0 - u1 < THR) || (u1 - u2 < THR) || (u2 - u3 < THR)) {
            int pos = atomicAdd(&g_flagcnt, 1);
            g_flags[pos] = b * NTOK + tok0 + t;
        }
    }
    __syncthreads();

    // ---- FUSED gather + pixel_shuffle write: thread handles token t>>2, quarter t&3 -
    {
        const int tt = t >> 2, qq = t & 3;
        int4 id = sidx[tt];
        const float* y0 = g_y + ((size_t)(b * NS) + id.x) * 192 + qq * 16;
        const float* y1 = g_y + ((size_t)(b * NS) + id.y) * 192 + 64 + qq * 16;
        const float* y2 = g_y + ((size_t)(b * NS) + id.z) * 192 + 128 + qq * 16;
        int n = tok0 + tt;
        int h1 = n >> 6, w1 = n & 63;
        float* ob = out + (size_t)b * C0 * (H0 * W0) + (2 * h1) * W0 + 2 * w1;
        #pragma unroll
        for (int part = 0; part < 4; part++) {
            float4 a = *(const float4*)(y0 + part * 4);
            float4 v1 = *(const float4*)(y1 + part * 4);
            float4 v2 = *(const float4*)(y2 + part * 4);
            a.x += v1.x + v2.x; a.y += v1.y + v2.y;
            a.z += v1.z + v2.z; a.w += v1.w + v2.w;
            int co = qq * 4 + part;
            *(float2*)(ob + (size_t)co * (H0 * W0))      = make_float2(a.x, a.y);
            *(float2*)(ob + (size_t)co * (H0 * W0) + W0) = make_float2(a.z, a.w);
        }
    }
}

// ---------------- kernel 5: rescue (R7-bit-identical fp32) + output rewrite ----------
__global__ __launch_bounds__(256) void rescue_kernel(float* __restrict__ out) {
    int cnt = g_flagcnt;
    if (cnt > B * NTOK) cnt = B * NTOK;
    const int nwarp = (gridDim.x * blockDim.x) >> 5;
    const int wgid  = (blockIdx.x * blockDim.x + threadIdx.x) >> 5;
    const int lane  = threadIdx.x & 31;

    for (int f = wgid; f < cnt; f += nwarp) {
        const int tokid = g_flags[f] & (B * NTOK - 1);
        const int b = tokid >> 12;
        float tv[64];
        const float4* tp = (const float4*)(g_xtok + (size_t)tokid * C1);
        #pragma unroll
        for (int j = 0; j < 16; j++) {
            float4 v = tp[j];
            tv[4 * j] = v.x; tv[4 * j + 1] = v.y; tv[4 * j + 2] = v.z; tv[4 * j + 3] = v.w;
        }
        float t0 = -3.4e38f, t1 = -3.4e38f, t2 = -3.4e38f;
        int   i0 = 0, i1 = 0, i2 = 0;
        #pragma unroll 1
        for (int mi = 0; mi < 8; mi++) {
            int m = mi * 32 + lane;
            const float4* xp = (const float4*)(g_xs + ((size_t)b * NS + m) * C1);
            float c0 = g_m2[b * NS + m];
            float c1 = 0.f, c2 = 0.f, c3 = 0.f, c4 = 0.f, c5 = 0.f, c6 = 0.f, c7 = 0.f;
            #pragma unroll
            for (int j = 0; j < 8; j++) {
                float4 xa = xp[2 * j];
                float4 xb = xp[2 * j + 1];
                c0 = fmaf(tv[8 * j + 0], xa.x, c0);
                c1 = fmaf(tv[8 * j + 1], xa.y, c1);
                c2 = fmaf(tv[8 * j + 2], xa.z, c2);
                c3 = fmaf(tv[8 * j + 3], xa.w, c3);
                c4 = fmaf(tv[8 * j + 4], xb.x, c4);
                c5 = fmaf(tv[8 * j + 5], xb.y, c5);
                c6 = fmaf(tv[8 * j + 6], xb.z, c6);
                c7 = fmaf(tv[8 * j + 7], xb.w, c7);
            }
            float slo = (c0 + c4) + (c2 + c6);
            float shi = (c1 + c5) + (c3 + c7);
            float s = slo + shi;
            INSERT3(s, m);
        }
        #pragma unroll
        for (int dx = 16; dx; dx >>= 1) {
            float o0 = __shfl_xor_sync(~0u, t0, dx), o1 = __shfl_xor_sync(~0u, t1, dx), o2 = __shfl_xor_sync(~0u, t2, dx);
            int   j0 = __shfl_xor_sync(~0u, i0, dx), j1 = __shfl_xor_sync(~0u, i1, dx), j2 = __shfl_xor_sync(~0u, i2, dx);
            INSERT3(o0, j0); INSERT3(o1, j1); INSERT3(o2, j2);
        }
        // all lanes now hold the final top-3; lanes 0-15 rewrite output (one co each)
        if (lane < 16) {
            const float* y0 = g_y + ((size_t)(b * NS) + i0) * 192 + lane * 4;
            const float* y1 = g_y + ((size_t)(b * NS) + i1) * 192 + 64 + lane * 4;
            const float* y2 = g_y + ((size_t)(b * NS) + i2) * 192 + 128 + lane * 4;
            float4 a = *(const float4*)y0;
            float4 v1 = *(const float4*)y1;
            float4 v2 = *(const float4*)y2;
            a.x += v1.x + v2.x; a.y += v1.y + v2.y;
            a.z += v1.z + v2.z; a.w += v1.w + v2.w;
            int n = tokid & (NTOK - 1);
            int h1 = n >> 6, w1 = n & 63;
            float* ob = out + (size_t)b * C0 * (H0 * W0) + (size_t)lane * (H0 * W0)
                      + (2 * h1) * W0 + 2 * w1;
            *(float2*)ob        = make_float2(a.x, a.y);
            *(float2*)(ob + W0) = make_float2(a.z, a.w);
        }
    }
}

// ---------------- launcher (score in slot 4 so ncu captures it) ----------------
extern "C" void kernel_launch(void* const* d_in, const int* in_sizes, int n_in,
                              void* d_out, int out_size) {
    const float* x    = (const float*)d_in[0];
    const float* w    = (const float*)d_in[1];
    const float* bias = (const float*)d_in[2];
    float* out = (float*)d_out;

    cudaFuncSetAttribute(score_mma_kernel,
                         cudaFuncAttributeMaxDynamicSharedMemorySize, SMEM_MMA);

    unshuffle_kernel<<<B * 64, 256>>>(x);
    sample_kernel<<<B * NS + 192, 64>>>(x, w);
    y_kernel<<<B * NS / 32, 192>>>(bias);
    score_mma_kernel<<<dim3(NTOK / MT, B), 512, SMEM_MMA>>>(out);
    rescue_kernel<<<256, 256>>>(out);
}